// round 3
// baseline (speedup 1.0000x reference)
#include <cuda_runtime.h>
#include <math_constants.h>

// MAM dense: C[m,n] = max_k(A[m,k]*W[n,k]) + min_k(A[m,k]*W[n,k]) + bias[n]
// plus argmax/argmin indices (written as float) if out_size has room for them.
//
// Compute-bound on FMA/ALU pipes (no tensor-core formulation exists for
// (max,+) semiring). Classic SGEMM-style register tiling:
//   block tile 128(M) x 64(N), 256 threads, 8x4 outputs per thread, BK=16.

#define BM 128
#define BN 64
#define BK 16
#define TM 8
#define TN 4
#define THREADS 256
#define APAD 4
#define WPAD 4

template <bool WIDX>
__global__ __launch_bounds__(THREADS)
void mam_kernel(const float* __restrict__ A, const float* __restrict__ W,
                const float* __restrict__ bias, float* __restrict__ out,
                int M, int N, int K) {
    __shared__ float As[BK][BM + APAD];   // K-major: As[kk][m]
    __shared__ float Ws[BK][BN + WPAD];   // K-major: Ws[kk][n]

    const int tid = threadIdx.x;
    const int tx = tid & 15;   // n direction, 16 threads
    const int ty = tid >> 4;   // m direction, 16 threads
    const int m0 = blockIdx.y * BM;
    const int n0 = blockIdx.x * BN;

    float vmax[TM][TN], vmin[TM][TN];
    int   imax[TM][TN], imin[TM][TN];

#pragma unroll
    for (int i = 0; i < TM; i++)
#pragma unroll
        for (int j = 0; j < TN; j++) {
            vmax[i][j] = -CUDART_INF_F;
            vmin[i][j] =  CUDART_INF_F;
            if (WIDX) { imax[i][j] = 0; imin[i][j] = 0; }
        }

    const float* Ablk = A + (size_t)m0 * K;
    const float* Wblk = W + (size_t)n0 * K;

    for (int k0 = 0; k0 < K; k0 += BK) {
        // ---- load A tile: BM x BK = 2048 elems, 8 per thread ----
#pragma unroll
        for (int r = 0; r < (BM * BK) / THREADS; r++) {
            int idx = tid + r * THREADS;
            int mm = idx >> 4;       // idx / BK
            int kk = idx & 15;       // idx % BK
            As[kk][mm] = Ablk[(size_t)mm * K + (k0 + kk)];
        }
        // ---- load W tile: BN x BK = 1024 elems, 4 per thread ----
#pragma unroll
        for (int r = 0; r < (BN * BK) / THREADS; r++) {
            int idx = tid + r * THREADS;
            int nn = idx >> 4;
            int kk = idx & 15;
            Ws[kk][nn] = Wblk[(size_t)nn * K + (k0 + kk)];
        }
        __syncthreads();

#pragma unroll 4
        for (int kk = 0; kk < BK; kk++) {
            float a[TM], w[TN];
            const float4 a0 = *reinterpret_cast<const float4*>(&As[kk][ty * TM]);
            const float4 a1 = *reinterpret_cast<const float4*>(&As[kk][ty * TM + 4]);
            const float4 w0 = *reinterpret_cast<const float4*>(&Ws[kk][tx * TN]);
            a[0] = a0.x; a[1] = a0.y; a[2] = a0.z; a[3] = a0.w;
            a[4] = a1.x; a[5] = a1.y; a[6] = a1.z; a[7] = a1.w;
            w[0] = w0.x; w[1] = w0.y; w[2] = w0.z; w[3] = w0.w;

            const int kg = k0 + kk;
#pragma unroll
            for (int i = 0; i < TM; i++) {
#pragma unroll
                for (int j = 0; j < TN; j++) {
                    float p = a[i] * w[j];
                    // strict compares => first-occurrence tie-break, matching
                    // jnp.argmax/argmin semantics exactly.
                    bool gm = p > vmax[i][j];
                    vmax[i][j] = gm ? p : vmax[i][j];
                    if (WIDX) imax[i][j] = gm ? kg : imax[i][j];
                    bool gn = p < vmin[i][j];
                    vmin[i][j] = gn ? p : vmin[i][j];
                    if (WIDX) imin[i][j] = gn ? kg : imin[i][j];
                }
            }
        }
        __syncthreads();
    }

    // ---- epilogue ----
    const size_t MN = (size_t)M * N;
    float bj[TN];
#pragma unroll
    for (int j = 0; j < TN; j++) bj[j] = bias[n0 + tx * TN + j];

#pragma unroll
    for (int i = 0; i < TM; i++) {
        int m = m0 + ty * TM + i;
        size_t row = (size_t)m * N + n0 + tx * TN;
        float4 c;
        c.x = vmax[i][0] + vmin[i][0] + bj[0];
        c.y = vmax[i][1] + vmin[i][1] + bj[1];
        c.z = vmax[i][2] + vmin[i][2] + bj[2];
        c.w = vmax[i][3] + vmin[i][3] + bj[3];
        *reinterpret_cast<float4*>(&out[row]) = c;
        if (WIDX) {
            float4 fx, fn;
            fx.x = (float)imax[i][0]; fx.y = (float)imax[i][1];
            fx.z = (float)imax[i][2]; fx.w = (float)imax[i][3];
            fn.x = (float)imin[i][0]; fn.y = (float)imin[i][1];
            fn.z = (float)imin[i][2]; fn.w = (float)imin[i][3];
            *reinterpret_cast<float4*>(&out[MN + row])     = fx;
            *reinterpret_cast<float4*>(&out[2 * MN + row]) = fn;
        }
    }
}

extern "C" void kernel_launch(void* const* d_in, const int* in_sizes, int n_in,
                              void* d_out, int out_size) {
    const float* x = (const float*)d_in[0];    // [M, K] flattened from [B,S,K]
    const float* w = (const float*)d_in[1];    // [N, K]
    const float* b = (const float*)d_in[2];    // [N]
    float* out = (float*)d_out;

    const int N = in_sizes[2];
    const int K = in_sizes[1] / N;
    const int M = in_sizes[0] / K;

    dim3 grid(N / BN, M / BM);
    const long long MN = (long long)M * (long long)N;

    if ((long long)out_size >= 3 * MN) {
        // harness compares (out, argmax, argmin) concatenated
        mam_kernel<true><<<grid, THREADS>>>(x, w, b, out, M, N, K);
    } else {
        // only the value output is checked
        mam_kernel<false><<<grid, THREADS>>>(x, w, b, out, M, N, K);
    }
}

// round 5
// speedup vs baseline: 1.3769x; 1.3769x over previous
#include <cuda_runtime.h>
#include <math_constants.h>
#include <stdint.h>

// ===========================================================================
// MAM dense: C[m,n] = max_k(A[m,k]*W[n,k]) + min_k(A[m,k]*W[n,k]) + bias[n]
// plus argmax/argmin index planes (as float).
//
// Fast path (M<=8192, N==1024, K==1024): exact candidate pruning.
//   P1/P2: per row of A (and of W) find threshold theta = smallest t with
//          #{|x_k| >= t} <= 64 (fp bisection), emit candidate (idx,val) lists
//          in ascending k, padded by repeating the last real candidate.
//   P3:    per output, scan only Ca(m) U Cw(n) (<=128 products), verify
//          vmax >= theta_a*theta_w*(1+1e-6) and vmin <= -that bound; if any
//          lane of a warp fails, the warp redoes the exact full K scan from
//          smem (always-correct overwrite). Tie-break exact: lists ascending,
//          strict compares, explicit min-index merge across the two lists.
// ===========================================================================

#define T_CAND 64
#define MAXM 8192
#define NW 1024

// device scratch (static allocation is allowed)
__device__ int   g_ca_idx[MAXM * T_CAND];
__device__ float g_ca_val[MAXM * T_CAND];
__device__ float g_th_a[MAXM];
__device__ int   g_cw_idx[NW * T_CAND];
__device__ float g_cw_val[NW * T_CAND];
__device__ float g_th_w[NW];

// ---------------------------------------------------------------------------
// P1/P2: per-row top-|x| candidate selection. One warp per row, K=1024 fixed.
// side: 0 -> write g_ca_*, 1 -> write g_cw_*
// ---------------------------------------------------------------------------
__global__ __launch_bounds__(256)
void topk_kernel(const float* __restrict__ X, int rows, int side) {
    const int warp = threadIdx.x >> 5;
    const int lane = threadIdx.x & 31;
    const int row = blockIdx.x * 8 + warp;
    if (row >= rows) return;
    const unsigned FULL = 0xffffffffu;

    int*   idxL = side ? g_cw_idx : g_ca_idx;
    float* valL = side ? g_cw_val : g_ca_val;
    float* thL  = side ? g_th_w   : g_th_a;

    // element order k = j*32 + lane (ascending-k emission later)
    float s[32], v[32];
    const float* Xr = X + (size_t)row * 1024;
#pragma unroll
    for (int j = 0; j < 32; j++) {
        s[j] = Xr[j * 32 + lane];
        v[j] = fabsf(s[j]);
    }

    // row max of |x|
    float rmax = 0.f;
#pragma unroll
    for (int j = 0; j < 32; j++) rmax = fmaxf(rmax, v[j]);
    for (int o = 16; o; o >>= 1) rmax = fmaxf(rmax, __shfl_xor_sync(FULL, rmax, o));

    // bisection: smallest t with count(|x| >= t) <= T_CAND
    float lo = 0.f, hi = rmax;
    for (int it = 0; it < 30; it++) {
        float mid = 0.5f * (lo + hi);
        int c = 0;
#pragma unroll
        for (int j = 0; j < 32; j++) c += (v[j] >= mid);
        for (int o = 16; o; o >>= 1) c += __shfl_xor_sync(FULL, c, o);
        if (c > T_CAND) lo = mid; else hi = mid;
    }
    const float theta = hi;  // count(>=theta) <= 64 guaranteed (hi invariant)

    // ascending-k compaction
    int slot = 0;
    int   bestpos = -1, bestidx = 0;
    float bestval = 0.f;
    int* myI = idxL + (size_t)row * T_CAND;
    float* myV = valL + (size_t)row * T_CAND;
#pragma unroll
    for (int j = 0; j < 32; j++) {
        bool pr = (v[j] >= theta);
        unsigned msk = __ballot_sync(FULL, pr);
        if (pr) {
            int pos = slot + __popc(msk & ((1u << lane) - 1u));
            myI[pos] = j * 32 + lane;
            myV[pos] = s[j];
            bestpos = pos; bestidx = j * 32 + lane; bestval = s[j];
        }
        slot += __popc(msk);
    }
    // warp argmax over bestpos -> the last real candidate (for padding)
    for (int o = 16; o; o >>= 1) {
        int   opos = __shfl_xor_sync(FULL, bestpos, o);
        int   oidx = __shfl_xor_sync(FULL, bestidx, o);
        float oval = __shfl_xor_sync(FULL, bestval, o);
        if (opos > bestpos) { bestpos = opos; bestidx = oidx; bestval = oval; }
    }
    // pad remaining slots by repeating last real candidate (exact self-tie)
    for (int p = slot + lane; p < T_CAND; p += 32) {
        myI[p] = bestidx;
        myV[p] = bestval;
    }
    if (lane == 0) thL[row] = theta;
}

// ---------------------------------------------------------------------------
// P3: candidate evaluation + verified bound + warp-level exact fallback.
// Block: MT=16 rows x NT=32 cols, 512 threads, 1 output/thread.
// ---------------------------------------------------------------------------
#define MT 16
#define NT 32
#define PITCH 1025   // 1025 % 32 == 1 -> conflict-free uniform-k access
#define CWPITCH 65   // 65 % 32 == 1

__global__ __launch_bounds__(512)
void mam_cand_kernel(const float* __restrict__ A, const float* __restrict__ W,
                     const float* __restrict__ bias, float* __restrict__ out,
                     int M, int widx) {
    extern __shared__ float smem[];
    float* sA   = smem;                    // MT * PITCH
    float* sW   = sA + MT * PITCH;         // NT * PITCH
    float* sCaV = sW + NT * PITCH;         // MT * T_CAND
    float* sCwV = sCaV + MT * T_CAND;      // NT * CWPITCH
    int*   sCaI = (int*)(sCwV + NT * CWPITCH);   // MT * T_CAND
    int*   sCwI = sCaI + MT * T_CAND;            // NT * CWPITCH
    float* sThA = (float*)(sCwI + NT * CWPITCH); // MT
    float* sThW = sThA + MT;                     // NT

    const int tid = threadIdx.x;
    const int m0 = blockIdx.y * MT;
    const int n0 = blockIdx.x * NT;

    // ---- load A tile rows (float4 from gmem, scalar STS into pitched rows) ----
    for (int i = tid; i < MT * 256; i += 512) {
        int r = i >> 8, c4 = i & 255;
        float4 t = reinterpret_cast<const float4*>(A + (size_t)(m0 + r) * 1024)[c4];
        float* d = sA + r * PITCH + c4 * 4;
        d[0] = t.x; d[1] = t.y; d[2] = t.z; d[3] = t.w;
    }
    // ---- load W tile rows ----
    for (int i = tid; i < NT * 256; i += 512) {
        int r = i >> 8, c4 = i & 255;
        float4 t = reinterpret_cast<const float4*>(W + (size_t)(n0 + r) * 1024)[c4];
        float* d = sW + r * PITCH + c4 * 4;
        d[0] = t.x; d[1] = t.y; d[2] = t.z; d[3] = t.w;
    }
    // ---- candidate lists + thetas ----
    for (int i = tid; i < MT * T_CAND; i += 512) {
        int r = i >> 6, j = i & 63;
        sCaI[i] = g_ca_idx[(size_t)(m0 + r) * T_CAND + j];
        sCaV[i] = g_ca_val[(size_t)(m0 + r) * T_CAND + j];
    }
    for (int i = tid; i < NT * T_CAND; i += 512) {
        int r = i >> 6, j = i & 63;
        sCwI[r * CWPITCH + j] = g_cw_idx[(size_t)(n0 + r) * T_CAND + j];
        sCwV[r * CWPITCH + j] = g_cw_val[(size_t)(n0 + r) * T_CAND + j];
    }
    if (tid < MT) sThA[tid] = g_th_a[m0 + tid];
    if (tid < NT) sThW[tid] = g_th_w[n0 + tid];
    __syncthreads();

    const int ml = tid >> 5;       // warp id = local m   (warp shares m)
    const int nl = tid & 31;       // lane    = local n
    const float* aRow = sA + ml * PITCH;
    const float* wRow = sW + nl * PITCH;

    const float NEGINF = -CUDART_INF_F;
    const float POSINF =  CUDART_INF_F;

    float vmax = NEGINF, vmin = POSINF;
    int   imax = 0, imin = 0;

    // ---- loop 1: Ca(m) candidates (warp-uniform k; wRow access conflict-free)
#pragma unroll 8
    for (int j = 0; j < T_CAND; j++) {
        int   k  = sCaI[ml * T_CAND + j];   // broadcast
        float av = sCaV[ml * T_CAND + j];   // broadcast
        float p  = av * wRow[k];
        bool g = p > vmax; vmax = g ? p : vmax; imax = g ? k : imax;
        bool l = p < vmin; vmin = l ? p : vmin; imin = l ? k : imin;
    }

    // ---- loop 2: Cw(n) candidates (per-lane k; separate accumulators)
    float vmax2 = NEGINF, vmin2 = POSINF;
    int   imax2 = 0, imin2 = 0;
#pragma unroll 8
    for (int j = 0; j < T_CAND; j++) {
        int   k  = sCwI[nl * CWPITCH + j];  // conflict-free
        float wv = sCwV[nl * CWPITCH + j];  // conflict-free
        float p  = aRow[k] * wv;            // scattered (random banks)
        bool g = p > vmax2; vmax2 = g ? p : vmax2; imax2 = g ? k : imax2;
        bool l = p < vmin2; vmin2 = l ? p : vmin2; imin2 = l ? k : imin2;
    }

    // ---- exact cross-list merge (handles ties by min index) ----
    if (vmax2 > vmax || (vmax2 == vmax && imax2 < imax)) { vmax = vmax2; imax = imax2; }
    if (vmin2 < vmin || (vmin2 == vmin && imin2 < imin)) { vmin = vmin2; imin = imin2; }

    // ---- soundness check; warp-level exact fallback on failure ----
    float bnd = sThA[ml] * sThW[nl] * 1.000001f;   // margin > fp rounding
    bool bad = !(vmax >= bnd && vmin <= -bnd);
    if (__any_sync(0xffffffffu, bad)) {
        vmax = NEGINF; vmin = POSINF; imax = 0; imin = 0;
#pragma unroll 8
        for (int k = 0; k < 1024; k++) {
            float p = aRow[k] * wRow[k];   // aRow broadcast, wRow conflict-free
            bool g = p > vmax; vmax = g ? p : vmax; imax = g ? k : imax;
            bool l = p < vmin; vmin = l ? p : vmin; imin = l ? k : imin;
        }
    }

    // ---- epilogue ----
    const int mg = m0 + ml, ng = n0 + nl;
    const size_t MN = (size_t)M * NW;
    const size_t o  = (size_t)mg * NW + ng;
    out[o] = vmax + vmin + bias[ng];
    if (widx) {
        out[MN + o]     = (float)imax;
        out[2 * MN + o] = (float)imin;
    }
}

// ---------------------------------------------------------------------------
// fallback exhaustive kernel (used only for unexpected shapes)
// ---------------------------------------------------------------------------
#define BM 128
#define BN 64
#define BK 16
#define TM 8
#define TN 4
#define THREADS 256

template <bool WIDX>
__global__ __launch_bounds__(THREADS)
void mam_kernel(const float* __restrict__ A, const float* __restrict__ W,
                const float* __restrict__ bias, float* __restrict__ out,
                int M, int N, int K) {
    __shared__ float As[BK][BM + 4];
    __shared__ float Ws[BK][BN + 4];
    const int tid = threadIdx.x;
    const int tx = tid & 15, ty = tid >> 4;
    const int m0 = blockIdx.y * BM, n0 = blockIdx.x * BN;
    float vmax[TM][TN], vmin[TM][TN];
    int   imax[TM][TN], imin[TM][TN];
#pragma unroll
    for (int i = 0; i < TM; i++)
#pragma unroll
        for (int j = 0; j < TN; j++) {
            vmax[i][j] = -CUDART_INF_F; vmin[i][j] = CUDART_INF_F;
            if (WIDX) { imax[i][j] = 0; imin[i][j] = 0; }
        }
    const float* Ablk = A + (size_t)m0 * K;
    const float* Wblk = W + (size_t)n0 * K;
    for (int k0 = 0; k0 < K; k0 += BK) {
#pragma unroll
        for (int r = 0; r < (BM * BK) / THREADS; r++) {
            int idx = tid + r * THREADS;
            As[idx & 15][idx >> 4] = Ablk[(size_t)(idx >> 4) * K + (k0 + (idx & 15))];
        }
#pragma unroll
        for (int r = 0; r < (BN * BK) / THREADS; r++) {
            int idx = tid + r * THREADS;
            Ws[idx & 15][idx >> 4] = Wblk[(size_t)(idx >> 4) * K + (k0 + (idx & 15))];
        }
        __syncthreads();
#pragma unroll 4
        for (int kk = 0; kk < BK; kk++) {
            float a[TM], w[TN];
#pragma unroll
            for (int i = 0; i < TM; i++) a[i] = As[kk][ty * TM + i];
#pragma unroll
            for (int j = 0; j < TN; j++) w[j] = Ws[kk][tx * TN + j];
            const int kg = k0 + kk;
#pragma unroll
            for (int i = 0; i < TM; i++)
#pragma unroll
                for (int j = 0; j < TN; j++) {
                    float p = a[i] * w[j];
                    bool gm = p > vmax[i][j];
                    vmax[i][j] = gm ? p : vmax[i][j];
                    if (WIDX) imax[i][j] = gm ? kg : imax[i][j];
                    bool gn = p < vmin[i][j];
                    vmin[i][j] = gn ? p : vmin[i][j];
                    if (WIDX) imin[i][j] = gn ? kg : imin[i][j];
                }
        }
        __syncthreads();
    }
    const size_t MN = (size_t)M * N;
#pragma unroll
    for (int i = 0; i < TM; i++) {
        int m = m0 + ty * TM + i;
        size_t row = (size_t)m * N + n0 + tx * TN;
#pragma unroll
        for (int j = 0; j < TN; j++) {
            out[row + j] = vmax[i][j] + vmin[i][j] + bias[n0 + tx * TN + j];
            if (WIDX) {
                out[MN + row + j] = (float)imax[i][j];
                out[2 * MN + row + j] = (float)imin[i][j];
            }
        }
    }
}

// ---------------------------------------------------------------------------
extern "C" void kernel_launch(void* const* d_in, const int* in_sizes, int n_in,
                              void* d_out, int out_size) {
    const float* x = (const float*)d_in[0];
    const float* w = (const float*)d_in[1];
    const float* b = (const float*)d_in[2];
    float* out = (float*)d_out;

    const int N = in_sizes[2];
    const int K = in_sizes[1] / N;
    const int M = in_sizes[0] / K;
    const long long MN = (long long)M * (long long)N;
    const int widx = ((long long)out_size >= 3 * MN) ? 1 : 0;

    if (K == 1024 && N == 1024 && M <= MAXM && (M % MT) == 0) {
        // P1: candidates of A rows, P2: candidates of W rows
        topk_kernel<<<(M + 7) / 8, 256>>>(x, M, 0);
        topk_kernel<<<(N + 7) / 8, 256>>>(w, N, 1);
        // P3
        size_t shmem = (size_t)(MT * PITCH + NT * PITCH + MT * T_CAND +
                                NT * CWPITCH + MT * T_CAND + NT * CWPITCH +
                                MT + NT) * 4;
        cudaFuncSetAttribute(mam_cand_kernel,
                             cudaFuncAttributeMaxDynamicSharedMemorySize,
                             (int)shmem);
        dim3 grid(N / NT, M / MT);
        mam_cand_kernel<<<grid, 512, shmem>>>(x, w, b, out, M, widx);
    } else {
        dim3 grid(N / BN, M / BM);
        if (widx) mam_kernel<true><<<grid, THREADS>>>(x, w, b, out, M, N, K);
        else      mam_kernel<false><<<grid, THREADS>>>(x, w, b, out, M, N, K);
    }
}

// round 6
// speedup vs baseline: 2.1919x; 1.5920x over previous
#include <cuda_runtime.h>
#include <math_constants.h>
#include <stdint.h>

// ===========================================================================
// MAM dense: C[m,n] = max_k(A[m,k]*W[n,k]) + min_k(A[m,k]*W[n,k]) + bias[n]
// plus argmax/argmin index planes (as float).
//
// Exact candidate pruning with DEFERRED sparse cleanup:
//   P0: zero worklist counter
//   P1/P2: per row of A / W: theta = smallest t with #{|x_k| >= t} <= 64
//          (fp bisection), emit candidate (k, val) int2 list ascending in k,
//          padded by repeating the last real candidate.
//   P3: per output scan Ca(m) U Cw(n) (<=128 products), verify
//       vmax >= th_a*th_w*(1+1e-6) and vmin <= -bound. Failing outputs are
//       pushed to a global worklist (NO in-warp rescan -> no SIMT blowup).
//   P4: cleanup kernel — one warp per failing pair, exact full-K scan from
//       gmem, overwrites the (value, argmax, argmin) of those outputs.
// Tie-break exactness: candidate lists ascending-k + strict compares; the
// cross-list merge and the cleanup warp-reduction both break value ties by
// minimum index, matching jnp.argmax/argmin first-occurrence semantics.
// ===========================================================================

#define T_CAND 64
#define MAXM 8192
#define NW 1024

__device__ int2  g_ca[MAXM * T_CAND];   // (k, float_bits) per A row
__device__ int2  g_cw[NW * T_CAND];     // (k, float_bits) per W row
__device__ float g_th_a[MAXM];
__device__ float g_th_w[NW];
__device__ int      g_cnt;
__device__ unsigned g_work[(size_t)MAXM * NW];  // worst-case capacity

// ---------------------------------------------------------------------------
__global__ void zero_cnt_kernel() {
    if (threadIdx.x == 0) g_cnt = 0;
}

// ---------------------------------------------------------------------------
// P1/P2: per-row top-|x| candidate selection. One warp per row, K=1024 fixed.
// ---------------------------------------------------------------------------
__global__ __launch_bounds__(256)
void topk_kernel(const float* __restrict__ X, int rows, int side) {
    const int warp = threadIdx.x >> 5;
    const int lane = threadIdx.x & 31;
    const int row = blockIdx.x * 8 + warp;
    if (row >= rows) return;
    const unsigned FULL = 0xffffffffu;

    int2*  lst = side ? g_cw : g_ca;
    float* thL = side ? g_th_w : g_th_a;

    float s[32], v[32];
    const float* Xr = X + (size_t)row * 1024;
#pragma unroll
    for (int j = 0; j < 32; j++) {
        s[j] = Xr[j * 32 + lane];
        v[j] = fabsf(s[j]);
    }

    float rmax = 0.f;
#pragma unroll
    for (int j = 0; j < 32; j++) rmax = fmaxf(rmax, v[j]);
    for (int o = 16; o; o >>= 1) rmax = fmaxf(rmax, __shfl_xor_sync(FULL, rmax, o));

    // bisection: smallest t with count(|x| >= t) <= T_CAND.
    // hi always keeps count <= T_CAND (invariant), so any iteration count is
    // sound; 22 iters resolves ~1e-6 which is far below order-stat gaps.
    float lo = 0.f, hi = rmax;
    for (int it = 0; it < 22; it++) {
        float mid = 0.5f * (lo + hi);
        int c = 0;
#pragma unroll
        for (int j = 0; j < 32; j++) c += (v[j] >= mid);
        for (int o = 16; o; o >>= 1) c += __shfl_xor_sync(FULL, c, o);
        if (c > T_CAND) lo = mid; else hi = mid;
    }
    const float theta = hi;

    // ascending-k compaction into int2 (k, bits(val))
    int slot = 0;
    int   bestpos = -1, bestidx = 0;
    float bestval = 0.f;
    int2* my = lst + (size_t)row * T_CAND;
#pragma unroll
    for (int j = 0; j < 32; j++) {
        bool pr = (v[j] >= theta);
        unsigned msk = __ballot_sync(FULL, pr);
        if (pr) {
            int pos = slot + __popc(msk & ((1u << lane) - 1u));
            my[pos] = make_int2(j * 32 + lane, __float_as_int(s[j]));
            bestpos = pos; bestidx = j * 32 + lane; bestval = s[j];
        }
        slot += __popc(msk);
    }
    for (int o = 16; o; o >>= 1) {
        int   opos = __shfl_xor_sync(FULL, bestpos, o);
        int   oidx = __shfl_xor_sync(FULL, bestidx, o);
        float oval = __shfl_xor_sync(FULL, bestval, o);
        if (opos > bestpos) { bestpos = opos; bestidx = oidx; bestval = oval; }
    }
    for (int p = slot + lane; p < T_CAND; p += 32)
        my[p] = make_int2(bestidx, __float_as_int(bestval));
    if (lane == 0) thL[row] = theta;
}

// ---------------------------------------------------------------------------
// P3: candidate evaluation; bad outputs -> worklist (no inline rescan).
// Block: MT=16 m x NT=32 n, 512 threads, 1 output/thread (warp shares m).
// ---------------------------------------------------------------------------
#define MT 16
#define NT 32
#define PITCH 1025   // floats; 1025 % 32 == 1 -> conflict-free uniform-k LDS
#define CW2   65     // int2 pitch; (r*65+j)*2 mod 32 = 2r+2j -> conflict-free

__global__ __launch_bounds__(512)
void mam_cand_kernel(const float* __restrict__ A, const float* __restrict__ W,
                     const float* __restrict__ bias, float* __restrict__ out,
                     int M, int widx) {
    extern __shared__ float smem[];
    float* sA  = smem;                         // MT * PITCH
    float* sW  = sA + MT * PITCH;              // NT * PITCH
    int2*  sCa = (int2*)(sW + NT * PITCH);     // MT * T_CAND
    int2*  sCw = sCa + MT * T_CAND;            // NT * CW2
    float* sThA = (float*)(sCw + NT * CW2);    // MT
    float* sThW = sThA + MT;                   // NT

    const int tid = threadIdx.x;
    const int m0 = blockIdx.y * MT;
    const int n0 = blockIdx.x * NT;
    const unsigned FULL = 0xffffffffu;

    for (int i = tid; i < MT * 256; i += 512) {
        int r = i >> 8, c4 = i & 255;
        float4 t = reinterpret_cast<const float4*>(A + (size_t)(m0 + r) * 1024)[c4];
        float* d = sA + r * PITCH + c4 * 4;
        d[0] = t.x; d[1] = t.y; d[2] = t.z; d[3] = t.w;
    }
    for (int i = tid; i < NT * 256; i += 512) {
        int r = i >> 8, c4 = i & 255;
        float4 t = reinterpret_cast<const float4*>(W + (size_t)(n0 + r) * 1024)[c4];
        float* d = sW + r * PITCH + c4 * 4;
        d[0] = t.x; d[1] = t.y; d[2] = t.z; d[3] = t.w;
    }
    for (int i = tid; i < MT * T_CAND; i += 512)
        sCa[i] = g_ca[(size_t)m0 * T_CAND + i];
    for (int i = tid; i < NT * T_CAND; i += 512) {
        int r = i >> 6, j = i & 63;
        sCw[r * CW2 + j] = g_cw[(size_t)(n0 + r) * T_CAND + j];
    }
    if (tid < MT) sThA[tid] = g_th_a[m0 + tid];
    if (tid < NT) sThW[tid] = g_th_w[n0 + tid];
    __syncthreads();

    const int ml = tid >> 5;
    const int nl = tid & 31;
    const float* aRow = sA + ml * PITCH;
    const float* wRow = sW + nl * PITCH;

    float vmax = -CUDART_INF_F, vmin = CUDART_INF_F;
    int   imax = 0, imin = 0;

    // loop 1: Ca(m) — warp-uniform candidate (LDS.64 broadcast), wRow conflict-free
    const int2* ca = sCa + ml * T_CAND;
#pragma unroll 8
    for (int j = 0; j < T_CAND; j++) {
        int2 pr = ca[j];
        float p = __int_as_float(pr.y) * wRow[pr.x];
        bool g = p > vmax; vmax = g ? p : vmax; imax = g ? pr.x : imax;
        bool l = p < vmin; vmin = l ? p : vmin; imin = l ? pr.x : imin;
    }

    // loop 2: Cw(n) — per-lane candidate (conflict-free LDS.64), aRow scattered
    float vmax2 = -CUDART_INF_F, vmin2 = CUDART_INF_F;
    int   imax2 = 0, imin2 = 0;
    const int2* cw = sCw + nl * CW2;
#pragma unroll 8
    for (int j = 0; j < T_CAND; j++) {
        int2 pr = cw[j];
        float p = aRow[pr.x] * __int_as_float(pr.y);
        bool g = p > vmax2; vmax2 = g ? p : vmax2; imax2 = g ? pr.x : imax2;
        bool l = p < vmin2; vmin2 = l ? p : vmin2; imin2 = l ? pr.x : imin2;
    }

    // exact cross-list merge (value ties -> min index)
    if (vmax2 > vmax || (vmax2 == vmax && imax2 < imax)) { vmax = vmax2; imax = imax2; }
    if (vmin2 < vmin || (vmin2 == vmin && imin2 < imin)) { vmin = vmin2; imin = imin2; }

    const int mg = m0 + ml, ng = n0 + nl;

    // soundness check -> worklist push (warp-aggregated)
    float bnd = sThA[ml] * sThW[nl] * 1.000001f;
    bool bad = !(vmax >= bnd && vmin <= -bnd);
    unsigned msk = __ballot_sync(FULL, bad);
    if (msk) {
        int base = 0;
        int leader = __ffs(msk) - 1;
        if (nl == leader) base = atomicAdd(&g_cnt, __popc(msk));
        base = __shfl_sync(FULL, base, leader);
        if (bad) {
            int pos = base + __popc(msk & ((1u << nl) - 1u));
            g_work[pos] = ((unsigned)mg << 10) | (unsigned)ng;
        }
    }

    const size_t MN = (size_t)M * NW;
    const size_t o  = (size_t)mg * NW + ng;
    out[o] = vmax + vmin + bias[ng];
    if (widx) {
        out[MN + o]     = (float)imax;
        out[2 * MN + o] = (float)imin;
    }
}

// ---------------------------------------------------------------------------
// P4: exact cleanup — one warp per failing (m,n). Lane L owns k in
// [32L, 32L+32) so lane order == k order; ties break toward smaller lane/idx.
// ---------------------------------------------------------------------------
__global__ __launch_bounds__(256)
void cleanup_kernel(const float* __restrict__ A, const float* __restrict__ W,
                    const float* __restrict__ bias, float* __restrict__ out,
                    int M, int widx) {
    const unsigned FULL = 0xffffffffu;
    const int lane = threadIdx.x & 31;
    const int gwarp = (blockIdx.x * blockDim.x + threadIdx.x) >> 5;
    const int nwarps = (gridDim.x * blockDim.x) >> 5;
    const int cnt = g_cnt;
    const size_t MN = (size_t)M * NW;

    for (int i = gwarp; i < cnt; i += nwarps) {
        unsigned e = g_work[i];
        int m = (int)(e >> 10), n = (int)(e & 1023u);
        const float4* Ar = reinterpret_cast<const float4*>(A + (size_t)m * 1024) + lane * 8;
        const float4* Wr = reinterpret_cast<const float4*>(W + (size_t)n * 1024) + lane * 8;

        float vmax = -CUDART_INF_F, vmin = CUDART_INF_F;
        int   imax = 0, imin = 0;
#pragma unroll
        for (int j = 0; j < 8; j++) {
            float4 a = Ar[j];
            float4 w = Wr[j];
            int k0 = lane * 32 + j * 4;
            float pv[4] = {a.x * w.x, a.y * w.y, a.z * w.z, a.w * w.w};
#pragma unroll
            for (int q = 0; q < 4; q++) {
                bool g = pv[q] > vmax; vmax = g ? pv[q] : vmax; imax = g ? (k0 + q) : imax;
                bool l = pv[q] < vmin; vmin = l ? pv[q] : vmin; imin = l ? (k0 + q) : imin;
            }
        }
        for (int o = 16; o; o >>= 1) {
            float ov = __shfl_xor_sync(FULL, vmax, o);
            int   oi = __shfl_xor_sync(FULL, imax, o);
            if (ov > vmax || (ov == vmax && oi < imax)) { vmax = ov; imax = oi; }
            float uv = __shfl_xor_sync(FULL, vmin, o);
            int   ui = __shfl_xor_sync(FULL, imin, o);
            if (uv < vmin || (uv == vmin && ui < imin)) { vmin = uv; imin = ui; }
        }
        if (lane == 0) {
            size_t o = (size_t)m * NW + n;
            out[o] = vmax + vmin + bias[n];
            if (widx) {
                out[MN + o]     = (float)imax;
                out[2 * MN + o] = (float)imin;
            }
        }
    }
}

// ---------------------------------------------------------------------------
// fallback exhaustive kernel (unexpected shapes only)
// ---------------------------------------------------------------------------
#define BM 128
#define BN 64
#define BK 16
#define TM 8
#define TN 4
#define THREADS 256

template <bool WIDX>
__global__ __launch_bounds__(THREADS)
void mam_kernel(const float* __restrict__ A, const float* __restrict__ W,
                const float* __restrict__ bias, float* __restrict__ out,
                int M, int N, int K) {
    __shared__ float As[BK][BM + 4];
    __shared__ float Ws[BK][BN + 4];
    const int tid = threadIdx.x;
    const int tx = tid & 15, ty = tid >> 4;
    const int m0 = blockIdx.y * BM, n0 = blockIdx.x * BN;
    float vmax[TM][TN], vmin[TM][TN];
    int   imax[TM][TN], imin[TM][TN];
#pragma unroll
    for (int i = 0; i < TM; i++)
#pragma unroll
        for (int j = 0; j < TN; j++) {
            vmax[i][j] = -CUDART_INF_F; vmin[i][j] = CUDART_INF_F;
            if (WIDX) { imax[i][j] = 0; imin[i][j] = 0; }
        }
    const float* Ablk = A + (size_t)m0 * K;
    const float* Wblk = W + (size_t)n0 * K;
    for (int k0 = 0; k0 < K; k0 += BK) {
#pragma unroll
        for (int r = 0; r < (BM * BK) / THREADS; r++) {
            int idx = tid + r * THREADS;
            As[idx & 15][idx >> 4] = Ablk[(size_t)(idx >> 4) * K + (k0 + (idx & 15))];
        }
#pragma unroll
        for (int r = 0; r < (BN * BK) / THREADS; r++) {
            int idx = tid + r * THREADS;
            Ws[idx & 15][idx >> 4] = Wblk[(size_t)(idx >> 4) * K + (k0 + (idx & 15))];
        }
        __syncthreads();
#pragma unroll 4
        for (int kk = 0; kk < BK; kk++) {
            float a[TM], w[TN];
#pragma unroll
            for (int i = 0; i < TM; i++) a[i] = As[kk][ty * TM + i];
#pragma unroll
            for (int j = 0; j < TN; j++) w[j] = Ws[kk][tx * TN + j];
            const int kg = k0 + kk;
#pragma unroll
            for (int i = 0; i < TM; i++)
#pragma unroll
                for (int j = 0; j < TN; j++) {
                    float p = a[i] * w[j];
                    bool gm = p > vmax[i][j];
                    vmax[i][j] = gm ? p : vmax[i][j];
                    if (WIDX) imax[i][j] = gm ? kg : imax[i][j];
                    bool gn = p < vmin[i][j];
                    vmin[i][j] = gn ? p : vmin[i][j];
                    if (WIDX) imin[i][j] = gn ? kg : imin[i][j];
                }
        }
        __syncthreads();
    }
    const size_t MN = (size_t)M * N;
#pragma unroll
    for (int i = 0; i < TM; i++) {
        int m = m0 + ty * TM + i;
        size_t row = (size_t)m * N + n0 + tx * TN;
#pragma unroll
        for (int j = 0; j < TN; j++) {
            out[row + j] = vmax[i][j] + vmin[i][j] + bias[n0 + tx * TN + j];
            if (WIDX) {
                out[MN + row + j] = (float)imax[i][j];
                out[2 * MN + row + j] = (float)imin[i][j];
            }
        }
    }
}

// ---------------------------------------------------------------------------
extern "C" void kernel_launch(void* const* d_in, const int* in_sizes, int n_in,
                              void* d_out, int out_size) {
    const float* x = (const float*)d_in[0];
    const float* w = (const float*)d_in[1];
    const float* b = (const float*)d_in[2];
    float* out = (float*)d_out;

    const int N = in_sizes[2];
    const int K = in_sizes[1] / N;
    const int M = in_sizes[0] / K;
    const long long MN = (long long)M * (long long)N;
    const int widx = ((long long)out_size >= 3 * MN) ? 1 : 0;

    if (K == 1024 && N == 1024 && M <= MAXM && (M % MT) == 0) {
        zero_cnt_kernel<<<1, 32>>>();
        topk_kernel<<<(M + 7) / 8, 256>>>(x, M, 0);
        topk_kernel<<<(N + 7) / 8, 256>>>(w, N, 1);

        size_t shmem = (size_t)(MT * PITCH + NT * PITCH) * 4 +
                       (size_t)(MT * T_CAND + NT * CW2) * 8 +
                       (size_t)(MT + NT) * 4;
        cudaFuncSetAttribute(mam_cand_kernel,
                             cudaFuncAttributeMaxDynamicSharedMemorySize,
                             (int)shmem);
        dim3 grid(N / NT, M / MT);
        mam_cand_kernel<<<grid, 512, shmem>>>(x, w, b, out, M, widx);

        cleanup_kernel<<<1184, 256>>>(x, w, b, out, M, widx);
    } else {
        dim3 grid(N / BN, M / BM);
        if (widx) mam_kernel<true><<<grid, THREADS>>>(x, w, b, out, M, N, K);
        else      mam_kernel<false><<<grid, THREADS>>>(x, w, b, out, M, N, K);
    }
}

// round 8
// speedup vs baseline: 3.3844x; 1.5440x over previous
#include <cuda_runtime.h>
#include <math_constants.h>
#include <stdint.h>

// ===========================================================================
// MAM dense: C[m,n] = max_k(A[m,k]*W[n,k]) + min_k(A[m,k]*W[n,k]) + bias[n]
// plus argmax/argmin index planes (as float).
//
// Pipeline (fast path K=N=1024, M%32==0):
//   P-1: transpose A -> At[k][m], W -> Wt[k][n] in gmem (coalesced both ways)
//   P0 : zero worklist counter
//   P1 : per-row top-64 |x| candidates (fp bisection threshold), ascending k,
//        padded with last real candidate; split index at k=512 stored.
//   P3 : candidate evaluation, both loops warp-uniform-k + conflict-free LDS:
//        loop1: warp=m, lanes=n, data sWt[k][n]; loop2: warp=n, lanes=m,
//        data sAt[k][m]; role transpose resolved via smem exchange.
//        Soundness check vs theta_a*theta_w; failures -> global worklist.
//   P4 : cleanup — one warp per failing (m,n), exact full-K scan.
// Exactness: ascending-k candidate order + strict compares; all merges break
// value ties by min index (jnp first-occurrence semantics). rel_err == 0.
// ===========================================================================

#define T_CAND 64
#define MAXM 8192
#define NW 1024
#define KC 512          // k-chunk
#define MTP 33          // tile pitch (odd -> conflict-free lanes-vary access)

__device__ float g_At[(size_t)MAXM * 1024];   // [K][M]
__device__ float g_Wt[(size_t)NW * 1024];     // [K][N]
__device__ int2  g_ca[MAXM * T_CAND];
__device__ int2  g_cw[NW * T_CAND];
__device__ float g_th_a[MAXM];
__device__ float g_th_w[NW];
__device__ int   g_spl_a[MAXM];
__device__ int   g_spl_w[NW];
__device__ int      g_cnt;
__device__ unsigned g_work[(size_t)MAXM * NW];

// ---------------------------------------------------------------------------
__global__ void zero_cnt_kernel() { if (threadIdx.x == 0) g_cnt = 0; }

// ---------------------------------------------------------------------------
// transpose X[R][C] -> Xt[C][R], coalesced both sides
// ---------------------------------------------------------------------------
__global__ __launch_bounds__(256)
void transpose_kernel(const float* __restrict__ X, float* __restrict__ Xt,
                      int R, int C) {
    __shared__ float t[32][33];
    const int c0 = blockIdx.x * 32, r0 = blockIdx.y * 32;
    const int x = threadIdx.x, y = threadIdx.y;   // 32 x 8
#pragma unroll
    for (int i = 0; i < 32; i += 8)
        t[y + i][x] = X[(size_t)(r0 + y + i) * C + c0 + x];
    __syncthreads();
#pragma unroll
    for (int i = 0; i < 32; i += 8)
        Xt[(size_t)(c0 + y + i) * R + r0 + x] = t[x][y + i];
}

// ---------------------------------------------------------------------------
// P1: per-row top-|x| candidates. One warp per row, K=1024 fixed.
// ---------------------------------------------------------------------------
__global__ __launch_bounds__(256)
void topk_kernel(const float* __restrict__ X, int rows, int side) {
    const int warp = threadIdx.x >> 5;
    const int lane = threadIdx.x & 31;
    const int row = blockIdx.x * 8 + warp;
    if (row >= rows) return;
    const unsigned FULL = 0xffffffffu;

    int2*  lst = side ? g_cw : g_ca;
    float* thL = side ? g_th_w : g_th_a;
    int*   spL = side ? g_spl_w : g_spl_a;

    float s[32], v[32];
    const float* Xr = X + (size_t)row * 1024;
#pragma unroll
    for (int j = 0; j < 32; j++) {
        s[j] = Xr[j * 32 + lane];
        v[j] = fabsf(s[j]);
    }

    float rmax = 0.f;
#pragma unroll
    for (int j = 0; j < 32; j++) rmax = fmaxf(rmax, v[j]);
    for (int o = 16; o; o >>= 1) rmax = fmaxf(rmax, __shfl_xor_sync(FULL, rmax, o));

    // bisection: smallest t with count(|x| >= t) <= T_CAND (hi keeps invariant)
    float lo = 0.f, hi = rmax;
    for (int it = 0; it < 22; it++) {
        float mid = 0.5f * (lo + hi);
        int c = 0;
#pragma unroll
        for (int j = 0; j < 32; j++) c += (v[j] >= mid);
        for (int o = 16; o; o >>= 1) c += __shfl_xor_sync(FULL, c, o);
        if (c > T_CAND) lo = mid; else hi = mid;
    }
    const float theta = hi;

    // ascending-k compaction; record split (count with k < 512)
    int slot = 0, slot16 = 0;
    int   bestpos = -1, bestidx = 0;
    float bestval = 0.f;
    int2* my = lst + (size_t)row * T_CAND;
#pragma unroll
    for (int j = 0; j < 32; j++) {
        bool pr = (v[j] >= theta);
        unsigned msk = __ballot_sync(FULL, pr);
        if (pr) {
            int pos = slot + __popc(msk & ((1u << lane) - 1u));
            my[pos] = make_int2(j * 32 + lane, __float_as_int(s[j]));
            bestpos = pos; bestidx = j * 32 + lane; bestval = s[j];
        }
        slot += __popc(msk);
        if (j == 15) slot16 = slot;   // k = 512 boundary
    }
    for (int o = 16; o; o >>= 1) {
        int   opos = __shfl_xor_sync(FULL, bestpos, o);
        int   oidx = __shfl_xor_sync(FULL, bestidx, o);
        float oval = __shfl_xor_sync(FULL, bestval, o);
        if (opos > bestpos) { bestpos = opos; bestidx = oidx; bestval = oval; }
    }
    for (int p = slot + lane; p < T_CAND; p += 32)
        my[p] = make_int2(bestidx, __float_as_int(bestval));
    if (lane == 0) {
        thL[row] = theta;
        // pads carry k = bestidx; list non-decreasing. Entries with k<512:
        spL[row] = (bestidx >= 512) ? slot16 : T_CAND;
    }
}

// ---------------------------------------------------------------------------
// P3: candidate evaluation, 32x32 outputs, 1024 threads, k chunked 2x512.
// ---------------------------------------------------------------------------
#define UPD(P, KK, VX, IX, VN, IN)                                   \
    { bool _g = (P) > (VX); (VX) = _g ? (P) : (VX); (IX) = _g ? (KK) : (IX); \
      bool _l = (P) < (VN); (VN) = _l ? (P) : (VN); (IN) = _l ? (KK) : (IN); }

__global__ __launch_bounds__(1024, 1)
void mam_cand_kernel(const float* __restrict__ bias, float* __restrict__ out,
                     int M, int widx) {
    extern __shared__ float smem[];
    float* sAt  = smem;                        // [KC][MTP]
    float* sWt  = sAt + KC * MTP;              // [KC][MTP]
    int2*  sCa  = (int2*)(sWt + KC * MTP);     // 32 * 64
    int2*  sCw  = sCa + 32 * T_CAND;           // 32 * 64
    float* sThA = (float*)(sCw + 32 * T_CAND); // 32
    float* sThW = sThA + 32;                   // 32
    int*   sSpA = (int*)(sThW + 32);           // 32
    int*   sSpW = sSpA + 32;                   // 32

    const int tid  = threadIdx.x;
    const int wid  = tid >> 5;
    const int lane = tid & 31;
    const int m0 = blockIdx.y * 32;
    const int n0 = blockIdx.x * 32;
    const unsigned FULL = 0xffffffffu;

    // candidate lists + metadata
    for (int i = tid; i < 32 * T_CAND; i += 1024) {
        sCa[i] = g_ca[(size_t)m0 * T_CAND + i];
        sCw[i] = g_cw[(size_t)n0 * T_CAND + i];
    }
    if (tid < 32) {
        sThA[tid] = g_th_a[m0 + tid];
        sThW[tid] = g_th_w[n0 + tid];
        sSpA[tid] = g_spl_a[m0 + tid];
        sSpW[tid] = g_spl_w[n0 + tid];
    }

    float vmax = -CUDART_INF_F, vmin = CUDART_INF_F;
    int   imax = 0, imin = 0;          // loop1 acc: output (m0+wid, n0+lane)
    float vmax2 = -CUDART_INF_F, vmin2 = CUDART_INF_F;
    int   imax2 = 0, imin2 = 0;        // loop2 acc: output (m0+lane, n0+wid)

#pragma unroll
    for (int c = 0; c < 2; c++) {
        __syncthreads();
        // fill k-major tiles: coalesced LDG, conflict-free STS (bank = k+lane)
        for (int k = wid; k < KC; k += 32) {
            sAt[k * MTP + lane] = g_At[(size_t)(c * KC + k) * M + m0 + lane];
            sWt[k * MTP + lane] = g_Wt[(size_t)(c * KC + k) * NW + n0 + lane];
        }
        __syncthreads();

        const int kbase = c * KC;

        // ---- loop1: warp = m (wid), lanes = n. Candidates of A row. ----
        {
            const int2* ca = sCa + wid * T_CAND;
            int jb = c ? sSpA[wid] : 0;
            int je = c ? T_CAND : sSpA[wid];
            int j = jb;
            if (j < je && (j & 1)) {
                int2 pr = ca[j];
                float p = __int_as_float(pr.y) * sWt[(pr.x - kbase) * MTP + lane];
                UPD(p, pr.x, vmax, imax, vmin, imin);
                j++;
            }
#pragma unroll 4
            for (; j + 1 < je; j += 2) {
                int4 q = *reinterpret_cast<const int4*>(ca + j);
                float p0 = __int_as_float(q.y) * sWt[(q.x - kbase) * MTP + lane];
                UPD(p0, q.x, vmax, imax, vmin, imin);
                float p1 = __int_as_float(q.w) * sWt[(q.z - kbase) * MTP + lane];
                UPD(p1, q.z, vmax, imax, vmin, imin);
            }
            if (j < je) {
                int2 pr = ca[j];
                float p = __int_as_float(pr.y) * sWt[(pr.x - kbase) * MTP + lane];
                UPD(p, pr.x, vmax, imax, vmin, imin);
            }
        }

        // ---- loop2: warp = n (wid), lanes = m. Candidates of W row. ----
        {
            const int2* cw = sCw + wid * T_CAND;
            int jb = c ? sSpW[wid] : 0;
            int je = c ? T_CAND : sSpW[wid];
            int j = jb;
            if (j < je && (j & 1)) {
                int2 pr = cw[j];
                float p = sAt[(pr.x - kbase) * MTP + lane] * __int_as_float(pr.y);
                UPD(p, pr.x, vmax2, imax2, vmin2, imin2);
                j++;
            }
#pragma unroll 4
            for (; j + 1 < je; j += 2) {
                int4 q = *reinterpret_cast<const int4*>(cw + j);
                float p0 = sAt[(q.x - kbase) * MTP + lane] * __int_as_float(q.y);
                UPD(p0, q.x, vmax2, imax2, vmin2, imin2);
                float p1 = sAt[(q.z - kbase) * MTP + lane] * __int_as_float(q.w);
                UPD(p1, q.z, vmax2, imax2, vmin2, imin2);
            }
            if (j < je) {
                int2 pr = cw[j];
                float p = sAt[(pr.x - kbase) * MTP + lane] * __int_as_float(pr.y);
                UPD(p, pr.x, vmax2, imax2, vmin2, imin2);
            }
        }
    }

    // ---- exchange loop2 results to loop1's thread mapping (overlay sAt) ----
    __syncthreads();
    int4* sX = (int4*)sAt;   // 32*33 int4 = 16.9KB < tile space
    sX[lane * 33 + wid] = make_int4(__float_as_int(vmax2), imax2,
                                    __float_as_int(vmin2), imin2);
    __syncthreads();
    {
        int4 e = sX[wid * 33 + lane];
        float xv = __int_as_float(e.x), nv = __int_as_float(e.z);
        if (xv > vmax || (xv == vmax && e.y < imax)) { vmax = xv; imax = e.y; }
        if (nv < vmin || (nv == vmin && e.w < imin)) { vmin = nv; imin = e.w; }
    }

    const int mg = m0 + wid, ng = n0 + lane;

    // ---- soundness check -> worklist (warp-aggregated) ----
    float bnd = sThA[wid] * sThW[lane] * 1.000001f;
    bool bad = !(vmax >= bnd && vmin <= -bnd);
    unsigned msk = __ballot_sync(FULL, bad);
    if (msk) {
        int base = 0;
        int leader = __ffs(msk) - 1;
        if (lane == leader) base = atomicAdd(&g_cnt, __popc(msk));
        base = __shfl_sync(FULL, base, leader);
        if (bad) {
            int pos = base + __popc(msk & ((1u << lane) - 1u));
            g_work[pos] = ((unsigned)mg << 10) | (unsigned)ng;
        }
    }

    const size_t MN = (size_t)M * NW;
    const size_t o  = (size_t)mg * NW + ng;
    out[o] = vmax + vmin + bias[ng];
    if (widx) {
        out[MN + o]     = (float)imax;
        out[2 * MN + o] = (float)imin;
    }
}

// ---------------------------------------------------------------------------
// P4: exact cleanup — one warp per failing (m,n).
// ---------------------------------------------------------------------------
__global__ __launch_bounds__(256)
void cleanup_kernel(const float* __restrict__ A, const float* __restrict__ W,
                    const float* __restrict__ bias, float* __restrict__ out,
                    int M, int widx) {
    const unsigned FULL = 0xffffffffu;
    const int lane = threadIdx.x & 31;
    const int gwarp = (blockIdx.x * blockDim.x + threadIdx.x) >> 5;
    const int nwarps = (gridDim.x * blockDim.x) >> 5;
    const int cnt = g_cnt;
    const size_t MN = (size_t)M * NW;

    for (int i = gwarp; i < cnt; i += nwarps) {
        unsigned e = g_work[i];
        int m = (int)(e >> 10), n = (int)(e & 1023u);
        const float4* Ar = reinterpret_cast<const float4*>(A + (size_t)m * 1024) + lane * 8;
        const float4* Wr = reinterpret_cast<const float4*>(W + (size_t)n * 1024) + lane * 8;

        float vmax = -CUDART_INF_F, vmin = CUDART_INF_F;
        int   imax = 0, imin = 0;
#pragma unroll
        for (int j = 0; j < 8; j++) {
            float4 a = Ar[j];
            float4 w = Wr[j];
            int k0 = lane * 32 + j * 4;
            float pv[4] = {a.x * w.x, a.y * w.y, a.z * w.z, a.w * w.w};
#pragma unroll
            for (int q = 0; q < 4; q++) {
                bool g = pv[q] > vmax; vmax = g ? pv[q] : vmax; imax = g ? (k0 + q) : imax;
                bool l = pv[q] < vmin; vmin = l ? pv[q] : vmin; imin = l ? (k0 + q) : imin;
            }
        }
        for (int o = 16; o; o >>= 1) {
            float ov = __shfl_xor_sync(FULL, vmax, o);
            int   oi = __shfl_xor_sync(FULL, imax, o);
            if (ov > vmax || (ov == vmax && oi < imax)) { vmax = ov; imax = oi; }
            float uv = __shfl_xor_sync(FULL, vmin, o);
            int   ui = __shfl_xor_sync(FULL, imin, o);
            if (uv < vmin || (uv == vmin && ui < imin)) { vmin = uv; imin = ui; }
        }
        if (lane == 0) {
            size_t o = (size_t)m * NW + n;
            out[o] = vmax + vmin + bias[n];
            if (widx) {
                out[MN + o]     = (float)imax;
                out[2 * MN + o] = (float)imin;
            }
        }
    }
}

// ---------------------------------------------------------------------------
// fallback exhaustive kernel (unexpected shapes only)
// ---------------------------------------------------------------------------
#define BM 128
#define BN 64
#define BK 16
#define TM 8
#define TN 4
#define THREADS 256

template <bool WIDX>
__global__ __launch_bounds__(THREADS)
void mam_kernel(const float* __restrict__ A, const float* __restrict__ W,
                const float* __restrict__ bias, float* __restrict__ out,
                int M, int N, int K) {
    __shared__ float As[BK][BM + 4];
    __shared__ float Ws[BK][BN + 4];
    const int tid = threadIdx.x;
    const int tx = tid & 15, ty = tid >> 4;
    const int m0 = blockIdx.y * BM, n0 = blockIdx.x * BN;
    float vmax[TM][TN], vmin[TM][TN];
    int   imax[TM][TN], imin[TM][TN];
#pragma unroll
    for (int i = 0; i < TM; i++)
#pragma unroll
        for (int j = 0; j < TN; j++) {
            vmax[i][j] = -CUDART_INF_F; vmin[i][j] = CUDART_INF_F;
            if (WIDX) { imax[i][j] = 0; imin[i][j] = 0; }
        }
    const float* Ablk = A + (size_t)m0 * K;
    const float* Wblk = W + (size_t)n0 * K;
    for (int k0 = 0; k0 < K; k0 += BK) {
#pragma unroll
        for (int r = 0; r < (BM * BK) / THREADS; r++) {
            int idx = tid + r * THREADS;
            As[idx & 15][idx >> 4] = Ablk[(size_t)(idx >> 4) * K + (k0 + (idx & 15))];
        }
#pragma unroll
        for (int r = 0; r < (BN * BK) / THREADS; r++) {
            int idx = tid + r * THREADS;
            Ws[idx & 15][idx >> 4] = Wblk[(size_t)(idx >> 4) * K + (k0 + (idx & 15))];
        }
        __syncthreads();
#pragma unroll 4
        for (int kk = 0; kk < BK; kk++) {
            float a[TM], w[TN];
#pragma unroll
            for (int i = 0; i < TM; i++) a[i] = As[kk][ty * TM + i];
#pragma unroll
            for (int j = 0; j < TN; j++) w[j] = Ws[kk][tx * TN + j];
            const int kg = k0 + kk;
#pragma unroll
            for (int i = 0; i < TM; i++)
#pragma unroll
                for (int j = 0; j < TN; j++) {
                    float p = a[i] * w[j];
                    bool gm = p > vmax[i][j];
                    vmax[i][j] = gm ? p : vmax[i][j];
                    if (WIDX) imax[i][j] = gm ? kg : imax[i][j];
                    bool gn = p < vmin[i][j];
                    vmin[i][j] = gn ? p : vmin[i][j];
                    if (WIDX) imin[i][j] = gn ? kg : imin[i][j];
                }
        }
        __syncthreads();
    }
    const size_t MN = (size_t)M * N;
#pragma unroll
    for (int i = 0; i < TM; i++) {
        int m = m0 + ty * TM + i;
        size_t row = (size_t)m * N + n0 + tx * TN;
#pragma unroll
        for (int j = 0; j < TN; j++) {
            out[row + j] = vmax[i][j] + vmin[i][j] + bias[n0 + tx * TN + j];
            if (WIDX) {
                out[MN + row + j] = (float)imax[i][j];
                out[2 * MN + row + j] = (float)imin[i][j];
            }
        }
    }
}

// ---------------------------------------------------------------------------
extern "C" void kernel_launch(void* const* d_in, const int* in_sizes, int n_in,
                              void* d_out, int out_size) {
    const float* x = (const float*)d_in[0];
    const float* w = (const float*)d_in[1];
    const float* b = (const float*)d_in[2];
    float* out = (float*)d_out;

    const int N = in_sizes[2];
    const int K = in_sizes[1] / N;
    const int M = in_sizes[0] / K;
    const long long MN = (long long)M * (long long)N;
    const int widx = ((long long)out_size >= 3 * MN) ? 1 : 0;

    if (K == 1024 && N == 1024 && M <= MAXM && (M % 32) == 0) {
        float* At; cudaGetSymbolAddress((void**)&At, g_At);
        float* Wt; cudaGetSymbolAddress((void**)&Wt, g_Wt);

        zero_cnt_kernel<<<1, 32>>>();
        {
            dim3 blk(32, 8);
            dim3 ga(1024 / 32, M / 32);
            transpose_kernel<<<ga, blk>>>(x, At, M, 1024);
            dim3 gw(1024 / 32, 1024 / 32);
            transpose_kernel<<<gw, blk>>>(w, Wt, 1024, 1024);
        }
        topk_kernel<<<(M + 7) / 8, 256>>>(x, M, 0);
        topk_kernel<<<(N + 7) / 8, 256>>>(w, N, 1);

        size_t shmem = (size_t)(2 * KC * MTP) * 4 +
                       (size_t)(2 * 32 * T_CAND) * 8 +
                       (size_t)(4 * 32) * 4;
        cudaFuncSetAttribute(mam_cand_kernel,
                             cudaFuncAttributeMaxDynamicSharedMemorySize,
                             (int)shmem);
        dim3 grid(N / 32, M / 32);
        mam_cand_kernel<<<grid, 1024, shmem>>>(b, out, M, widx);

        cleanup_kernel<<<1184, 256>>>(x, w, b, out, M, widx);
    } else {
        dim3 grid(N / BN, M / BM);
        if (widx) mam_kernel<true><<<grid, THREADS>>>(x, w, b, out, M, N, K);
        else      mam_kernel<false><<<grid, THREADS>>>(x, w, b, out, M, N, K);
    }
}

// round 11
// speedup vs baseline: 3.8387x; 1.1342x over previous
#include <cuda_runtime.h>
#include <math_constants.h>
#include <stdint.h>

// ===========================================================================
// MAM dense: C[m,n] = max_k(A[m,k]*W[n,k]) + min_k(A[m,k]*W[n,k]) + bias[n]
// plus argmax/argmin index planes (as float).
//
// Pipeline (fast path K=N=1024, M%32==0):
//   P-1: transpose A -> At[k][m], W -> Wt[k][n] in gmem (coalesced both ways)
//   P0 : zero worklist counter
//   P1 : per-row top-64 |x| candidates (fp bisection threshold), ascending k,
//        padded with last real candidate; int4 split counts at k=256/512/768.
//   P3 : candidate evaluation, 32x32 outputs/block, 1024 thr, k in 4 chunks
//        of 256 (small tiles -> 2 blocks/SM = 100% occupancy).
//        loop1: warp=m, lanes=n, data sWt[k][n]; loop2: warp=n, lanes=m,
//        data sAt[k][m]; role transpose resolved via smem exchange.
//        Soundness check vs theta_a*theta_w; failures -> global worklist.
//   P4 : cleanup — one warp per failing (m,n), exact full-K scan.
// Exactness: ascending-k candidate order + strict compares; all merges break
// value ties by min index (jnp first-occurrence semantics). rel_err == 0.
// ===========================================================================

#define T_CAND 64
#define MAXM 8192
#define NW 1024
#define KC 256          // k-chunk (4 chunks of 256)
#define NCH 4
#define MTP 33          // tile pitch (odd -> conflict-free lanes-vary access)

__device__ float g_At[(size_t)MAXM * 1024];   // [K][M]
__device__ float g_Wt[(size_t)NW * 1024];     // [K][N]
__device__ int2  g_ca[MAXM * T_CAND];
__device__ int2  g_cw[NW * T_CAND];
__device__ float g_th_a[MAXM];
__device__ float g_th_w[NW];
__device__ int4  g_spl_a[MAXM];   // cand counts with k <256,<512,<768, 64
__device__ int4  g_spl_w[NW];
__device__ int      g_cnt;
__device__ unsigned g_work[(size_t)MAXM * NW];

// ---------------------------------------------------------------------------
__global__ void zero_cnt_kernel() { if (threadIdx.x == 0) g_cnt = 0; }

// ---------------------------------------------------------------------------
// transpose X[R][C] -> Xt[C][R], coalesced both sides
// ---------------------------------------------------------------------------
__global__ __launch_bounds__(256)
void transpose_kernel(const float* __restrict__ X, float* __restrict__ Xt,
                      int R, int C) {
    __shared__ float t[32][33];
    const int c0 = blockIdx.x * 32, r0 = blockIdx.y * 32;
    const int x = threadIdx.x, y = threadIdx.y;   // 32 x 8
#pragma unroll
    for (int i = 0; i < 32; i += 8)
        t[y + i][x] = X[(size_t)(r0 + y + i) * C + c0 + x];
    __syncthreads();
#pragma unroll
    for (int i = 0; i < 32; i += 8)
        Xt[(size_t)(c0 + y + i) * R + r0 + x] = t[x][y + i];
}

// ---------------------------------------------------------------------------
// P1: per-row top-|x| candidates. One warp per row, K=1024 fixed.
// ---------------------------------------------------------------------------
__global__ __launch_bounds__(256)
void topk_kernel(const float* __restrict__ X, int rows, int side) {
    const int warp = threadIdx.x >> 5;
    const int lane = threadIdx.x & 31;
    const int row = blockIdx.x * 8 + warp;
    if (row >= rows) return;
    const unsigned FULL = 0xffffffffu;

    int2*  lst = side ? g_cw : g_ca;
    float* thL = side ? g_th_w : g_th_a;
    int4*  spL = side ? g_spl_w : g_spl_a;

    float s[32], v[32];
    const float* Xr = X + (size_t)row * 1024;
#pragma unroll
    for (int j = 0; j < 32; j++) {
        s[j] = Xr[j * 32 + lane];
        v[j] = fabsf(s[j]);
    }

    float rmax = 0.f;
#pragma unroll
    for (int j = 0; j < 32; j++) rmax = fmaxf(rmax, v[j]);
    for (int o = 16; o; o >>= 1) rmax = fmaxf(rmax, __shfl_xor_sync(FULL, rmax, o));

    // bisection: smallest t with count(|x| >= t) <= T_CAND (hi keeps invariant)
    float lo = 0.f, hi = rmax;
    for (int it = 0; it < 16; it++) {
        float mid = 0.5f * (lo + hi);
        int c = 0;
#pragma unroll
        for (int j = 0; j < 32; j++) c += (v[j] >= mid);
        for (int o = 16; o; o >>= 1) c += __shfl_xor_sync(FULL, c, o);
        if (c > T_CAND) lo = mid; else hi = mid;
    }
    const float theta = hi;

    // ascending-k compaction; record chunk split counts at j=8,16,24
    int slot = 0;
    int s256 = 0, s512 = 0, s768 = 0;
    int   bestpos = -1, bestidx = 0;
    float bestval = 0.f;
    int2* my = lst + (size_t)row * T_CAND;
#pragma unroll
    for (int j = 0; j < 32; j++) {
        bool pr = (v[j] >= theta);
        unsigned msk = __ballot_sync(FULL, pr);
        if (pr) {
            int pos = slot + __popc(msk & ((1u << lane) - 1u));
            my[pos] = make_int2(j * 32 + lane, __float_as_int(s[j]));
            bestpos = pos; bestidx = j * 32 + lane; bestval = s[j];
        }
        slot += __popc(msk);
        if (j == 7)  s256 = slot;
        if (j == 15) s512 = slot;
        if (j == 23) s768 = slot;
    }
    for (int o = 16; o; o >>= 1) {
        int   opos = __shfl_xor_sync(FULL, bestpos, o);
        int   oidx = __shfl_xor_sync(FULL, bestidx, o);
        float oval = __shfl_xor_sync(FULL, bestval, o);
        if (opos > bestpos) { bestpos = opos; bestidx = oidx; bestval = oval; }
    }
    for (int p = slot + lane; p < T_CAND; p += 32)
        my[p] = make_int2(bestidx, __float_as_int(bestval));
    if (lane == 0) {
        thL[row] = theta;
        // pads carry k = bestidx (largest k in list, ascending preserved).
        // entries with k < boundary: real count, or all 64 if bestidx < b.
        int4 sp;
        sp.x = (bestidx < 256) ? T_CAND : s256;
        sp.y = (bestidx < 512) ? T_CAND : s512;
        sp.z = (bestidx < 768) ? T_CAND : s768;
        sp.w = T_CAND;
        spL[row] = sp;
    }
}

// ---------------------------------------------------------------------------
// P3: candidate evaluation, 32x32 outputs, 1024 threads, k in 4 chunks of 256.
// ---------------------------------------------------------------------------
#define UPD(P, KK, VX, IX, VN, IN)                                   \
    { bool _g = (P) > (VX); (VX) = _g ? (P) : (VX); (IX) = _g ? (KK) : (IX); \
      bool _l = (P) < (VN); (VN) = _l ? (P) : (VN); (IN) = _l ? (KK) : (IN); }

__global__ __launch_bounds__(1024, 2)
void mam_cand_kernel(const float* __restrict__ bias, float* __restrict__ out,
                     int M, int widx) {
    extern __shared__ float smem[];
    float* sAt  = smem;                        // [KC][MTP]
    float* sWt  = sAt + KC * MTP;              // [KC][MTP]
    int2*  sCa  = (int2*)(sWt + KC * MTP);     // 32 * 64
    int2*  sCw  = sCa + 32 * T_CAND;           // 32 * 64
    float* sThA = (float*)(sCw + 32 * T_CAND); // 32
    float* sThW = sThA + 32;                   // 32
    int*   sSpA = (int*)(sThW + 32);           // 32 * 5 (cum splits)
    int*   sSpW = sSpA + 32 * 5;               // 32 * 5

    const int tid  = threadIdx.x;
    const int wid  = tid >> 5;
    const int lane = tid & 31;
    const int m0 = blockIdx.y * 32;
    const int n0 = blockIdx.x * 32;
    const unsigned FULL = 0xffffffffu;

    // candidate lists + metadata
    for (int i = tid; i < 32 * T_CAND; i += 1024) {
        sCa[i] = g_ca[(size_t)m0 * T_CAND + i];
        sCw[i] = g_cw[(size_t)n0 * T_CAND + i];
    }
    if (tid < 32) {
        sThA[tid] = g_th_a[m0 + tid];
        sThW[tid] = g_th_w[n0 + tid];
        int4 sa = g_spl_a[m0 + tid];
        sSpA[tid * 5 + 0] = 0; sSpA[tid * 5 + 1] = sa.x;
        sSpA[tid * 5 + 2] = sa.y; sSpA[tid * 5 + 3] = sa.z;
        sSpA[tid * 5 + 4] = sa.w;
        int4 sw = g_spl_w[n0 + tid];
        sSpW[tid * 5 + 0] = 0; sSpW[tid * 5 + 1] = sw.x;
        sSpW[tid * 5 + 2] = sw.y; sSpW[tid * 5 + 3] = sw.z;
        sSpW[tid * 5 + 4] = sw.w;
    }

    float vmax = -CUDART_INF_F, vmin = CUDART_INF_F;
    int   imax = 0, imin = 0;          // loop1 acc: output (m0+wid, n0+lane)
    float vmax2 = -CUDART_INF_F, vmin2 = CUDART_INF_F;
    int   imax2 = 0, imin2 = 0;        // loop2 acc: output (m0+lane, n0+wid)

#pragma unroll 1
    for (int c = 0; c < NCH; c++) {
        __syncthreads();
        // fill k-major tiles: coalesced LDG, conflict-free STS (bank = k+lane)
#pragma unroll
        for (int k = wid; k < KC; k += 32) {
            sAt[k * MTP + lane] = g_At[(size_t)(c * KC + k) * M + m0 + lane];
            sWt[k * MTP + lane] = g_Wt[(size_t)(c * KC + k) * NW + n0 + lane];
        }
        __syncthreads();

        const int kbase = c * KC;

        // ---- loop1: warp = m (wid), lanes = n. Candidates of A row. ----
        {
            const int2* ca = sCa + wid * T_CAND;
            int jb = sSpA[wid * 5 + c];
            int je = sSpA[wid * 5 + c + 1];
            int j = jb;
            if (j < je && (j & 1)) {
                int2 pr = ca[j];
                float p = __int_as_float(pr.y) * sWt[(pr.x - kbase) * MTP + lane];
                UPD(p, pr.x, vmax, imax, vmin, imin);
                j++;
            }
#pragma unroll 4
            for (; j + 1 < je; j += 2) {
                int4 q = *reinterpret_cast<const int4*>(ca + j);
                float p0 = __int_as_float(q.y) * sWt[(q.x - kbase) * MTP + lane];
                UPD(p0, q.x, vmax, imax, vmin, imin);
                float p1 = __int_as_float(q.w) * sWt[(q.z - kbase) * MTP + lane];
                UPD(p1, q.z, vmax, imax, vmin, imin);
            }
            if (j < je) {
                int2 pr = ca[j];
                float p = __int_as_float(pr.y) * sWt[(pr.x - kbase) * MTP + lane];
                UPD(p, pr.x, vmax, imax, vmin, imin);
            }
        }

        // ---- loop2: warp = n (wid), lanes = m. Candidates of W row. ----
        {
            const int2* cw = sCw + wid * T_CAND;
            int jb = sSpW[wid * 5 + c];
            int je = sSpW[wid * 5 + c + 1];
            int j = jb;
            if (j < je && (j & 1)) {
                int2 pr = cw[j];
                float p = sAt[(pr.x - kbase) * MTP + lane] * __int_as_float(pr.y);
                UPD(p, pr.x, vmax2, imax2, vmin2, imin2);
                j++;
            }
#pragma unroll 4
            for (; j + 1 < je; j += 2) {
                int4 q = *reinterpret_cast<const int4*>(cw + j);
                float p0 = sAt[(q.x - kbase) * MTP + lane] * __int_as_float(q.y);
                UPD(p0, q.x, vmax2, imax2, vmin2, imin2);
                float p1 = sAt[(q.z - kbase) * MTP + lane] * __int_as_float(q.w);
                UPD(p1, q.z, vmax2, imax2, vmin2, imin2);
            }
            if (j < je) {
                int2 pr = cw[j];
                float p = sAt[(pr.x - kbase) * MTP + lane] * __int_as_float(pr.y);
                UPD(p, pr.x, vmax2, imax2, vmin2, imin2);
            }
        }
    }

    // ---- exchange loop2 results to loop1's thread mapping (overlay sAt) ----
    __syncthreads();
    int4* sX = (int4*)sAt;   // 32*33 int4 = 16.9KB < tile space
    sX[lane * 33 + wid] = make_int4(__float_as_int(vmax2), imax2,
                                    __float_as_int(vmin2), imin2);
    __syncthreads();
    {
        int4 e = sX[wid * 33 + lane];
        float xv = __int_as_float(e.x), nv = __int_as_float(e.z);
        if (xv > vmax || (xv == vmax && e.y < imax)) { vmax = xv; imax = e.y; }
        if (nv < vmin || (nv == vmin && e.w < imin)) { vmin = nv; imin = e.w; }
    }

    const int mg = m0 + wid, ng = n0 + lane;

    // ---- soundness check -> worklist (warp-aggregated) ----
    float bnd = sThA[wid] * sThW[lane] * 1.000001f;
    bool bad = !(vmax >= bnd && vmin <= -bnd);
    unsigned msk = __ballot_sync(FULL, bad);
    if (msk) {
        int base = 0;
        int leader = __ffs(msk) - 1;
        if (lane == leader) base = atomicAdd(&g_cnt, __popc(msk));
        base = __shfl_sync(FULL, base, leader);
        if (bad) {
            int pos = base + __popc(msk & ((1u << lane) - 1u));
            g_work[pos] = ((unsigned)mg << 10) | (unsigned)ng;
        }
    }

    const size_t MN = (size_t)M * NW;
    const size_t o  = (size_t)mg * NW + ng;
    out[o] = vmax + vmin + bias[ng];
    if (widx) {
        out[MN + o]     = (float)imax;
        out[2 * MN + o] = (float)imin;
    }
}

// ---------------------------------------------------------------------------
// P4: exact cleanup — one warp per failing (m,n).
// ---------------------------------------------------------------------------
__global__ __launch_bounds__(256)
void cleanup_kernel(const float* __restrict__ A, const float* __restrict__ W,
                    const float* __restrict__ bias, float* __restrict__ out,
                    int M, int widx) {
    const unsigned FULL = 0xffffffffu;
    const int lane = threadIdx.x & 31;
    const int gwarp = (blockIdx.x * blockDim.x + threadIdx.x) >> 5;
    const int nwarps = (gridDim.x * blockDim.x) >> 5;
    const int cnt = g_cnt;
    const size_t MN = (size_t)M * NW;

    for (int i = gwarp; i < cnt; i += nwarps) {
        unsigned e = g_work[i];
        int m = (int)(e >> 10), n = (int)(e & 1023u);
        const float4* Ar = reinterpret_cast<const float4*>(A + (size_t)m * 1024) + lane * 8;
        const float4* Wr = reinterpret_cast<const float4*>(W + (size_t)n * 1024) + lane * 8;

        float vmax = -CUDART_INF_F, vmin = CUDART_INF_F;
        int   imax = 0, imin = 0;
#pragma unroll
        for (int j = 0; j < 8; j++) {
            float4 a = Ar[j];
            float4 w = Wr[j];
            int k0 = lane * 32 + j * 4;
            float pv[4] = {a.x * w.x, a.y * w.y, a.z * w.z, a.w * w.w};
#pragma unroll
            for (int q = 0; q < 4; q++) {
                bool g = pv[q] > vmax; vmax = g ? pv[q] : vmax; imax = g ? (k0 + q) : imax;
                bool l = pv[q] < vmin; vmin = l ? pv[q] : vmin; imin = l ? (k0 + q) : imin;
            }
        }
        for (int o = 16; o; o >>= 1) {
            float ov = __shfl_xor_sync(FULL, vmax, o);
            int   oi = __shfl_xor_sync(FULL, imax, o);
            if (ov > vmax || (ov == vmax && oi < imax)) { vmax = ov; imax = oi; }
            float uv = __shfl_xor_sync(FULL, vmin, o);
            int   ui = __shfl_xor_sync(FULL, imin, o);
            if (uv < vmin || (uv == vmin && ui < imin)) { vmin = uv; imin = ui; }
        }
        if (lane == 0) {
            size_t o = (size_t)m * NW + n;
            out[o] = vmax + vmin + bias[n];
            if (widx) {
                out[MN + o]     = (float)imax;
                out[2 * MN + o] = (float)imin;
            }
        }
    }
}

// ---------------------------------------------------------------------------
// fallback exhaustive kernel (unexpected shapes only)
// ---------------------------------------------------------------------------
#define BM 128
#define BN 64
#define BK 16
#define TM 8
#define TN 4
#define THREADS 256

template <bool WIDX>
__global__ __launch_bounds__(THREADS)
void mam_kernel(const float* __restrict__ A, const float* __restrict__ W,
                const float* __restrict__ bias, float* __restrict__ out,
                int M, int N, int K) {
    __shared__ float As[BK][BM + 4];
    __shared__ float Ws[BK][BN + 4];
    const int tid = threadIdx.x;
    const int tx = tid & 15, ty = tid >> 4;
    const int m0 = blockIdx.y * BM, n0 = blockIdx.x * BN;
    float vmax[TM][TN], vmin[TM][TN];
    int   imax[TM][TN], imin[TM][TN];
#pragma unroll
    for (int i = 0; i < TM; i++)
#pragma unroll
        for (int j = 0; j < TN; j++) {
            vmax[i][j] = -CUDART_INF_F; vmin[i][j] = CUDART_INF_F;
            if (WIDX) { imax[i][j] = 0; imin[i][j] = 0; }
        }
    const float* Ablk = A + (size_t)m0 * K;
    const float* Wblk = W + (size_t)n0 * K;
    for (int k0 = 0; k0 < K; k0 += BK) {
#pragma unroll
        for (int r = 0; r < (BM * BK) / THREADS; r++) {
            int idx = tid + r * THREADS;
            As[idx & 15][idx >> 4] = Ablk[(size_t)(idx >> 4) * K + (k0 + (idx & 15))];
        }
#pragma unroll
        for (int r = 0; r < (BN * BK) / THREADS; r++) {
            int idx = tid + r * THREADS;
            Ws[idx & 15][idx >> 4] = Wblk[(size_t)(idx >> 4) * K + (k0 + (idx & 15))];
        }
        __syncthreads();
#pragma unroll 4
        for (int kk = 0; kk < BK; kk++) {
            float a[TM], w[TN];
#pragma unroll
            for (int i = 0; i < TM; i++) a[i] = As[kk][ty * TM + i];
#pragma unroll
            for (int j = 0; j < TN; j++) w[j] = Ws[kk][tx * TN + j];
            const int kg = k0 + kk;
#pragma unroll
            for (int i = 0; i < TM; i++)
#pragma unroll
                for (int j = 0; j < TN; j++) {
                    float p = a[i] * w[j];
                    bool gm = p > vmax[i][j];
                    vmax[i][j] = gm ? p : vmax[i][j];
                    if (WIDX) imax[i][j] = gm ? kg : imax[i][j];
                    bool gn = p < vmin[i][j];
                    vmin[i][j] = gn ? p : vmin[i][j];
                    if (WIDX) imin[i][j] = gn ? kg : imin[i][j];
                }
        }
        __syncthreads();
    }
    const size_t MN = (size_t)M * N;
#pragma unroll
    for (int i = 0; i < TM; i++) {
        int m = m0 + ty * TM + i;
        size_t row = (size_t)m * N + n0 + tx * TN;
#pragma unroll
        for (int j = 0; j < TN; j++) {
            out[row + j] = vmax[i][j] + vmin[i][j] + bias[n0 + tx * TN + j];
            if (WIDX) {
                out[MN + row + j] = (float)imax[i][j];
                out[2 * MN + row + j] = (float)imin[i][j];
            }
        }
    }
}

// ---------------------------------------------------------------------------
extern "C" void kernel_launch(void* const* d_in, const int* in_sizes, int n_in,
                              void* d_out, int out_size) {
    const float* x = (const float*)d_in[0];
    const float* w = (const float*)d_in[1];
    const float* b = (const float*)d_in[2];
    float* out = (float*)d_out;

    const int N = in_sizes[2];
    const int K = in_sizes[1] / N;
    const int M = in_sizes[0] / K;
    const long long MN = (long long)M * (long long)N;
    const int widx = ((long long)out_size >= 3 * MN) ? 1 : 0;

    if (K == 1024 && N == 1024 && M <= MAXM && (M % 32) == 0) {
        float* At; cudaGetSymbolAddress((void**)&At, g_At);
        float* Wt; cudaGetSymbolAddress((void**)&Wt, g_Wt);

        zero_cnt_kernel<<<1, 32>>>();
        {
            dim3 blk(32, 8);
            dim3 ga(1024 / 32, M / 32);
            transpose_kernel<<<ga, blk>>>(x, At, M, 1024);
            dim3 gw(1024 / 32, 1024 / 32);
            transpose_kernel<<<gw, blk>>>(w, Wt, 1024, 1024);
        }
        topk_kernel<<<(M + 7) / 8, 256>>>(x, M, 0);
        topk_kernel<<<(N + 7) / 8, 256>>>(w, N, 1);

        size_t shmem = (size_t)(2 * KC * MTP) * 4 +       // tiles (67.6KB)
                       (size_t)(2 * 32 * T_CAND) * 8 +    // candidate lists
                       (size_t)(2 * 32) * 4 +             // thetas
                       (size_t)(2 * 32 * 5) * 4;          // cum splits
        cudaFuncSetAttribute(mam_cand_kernel,
                             cudaFuncAttributeMaxDynamicSharedMemorySize,
                             (int)shmem);
        dim3 grid(N / 32, M / 32);
        mam_cand_kernel<<<grid, 1024, shmem>>>(b, out, M, widx);

        cleanup_kernel<<<1184, 256>>>(x, w, b, out, M, widx);
    } else {
        dim3 grid(N / BN, M / BM);
        if (widx) mam_kernel<true><<<grid, THREADS>>>(x, w, b, out, M, N, K);
        else      mam_kernel<false><<<grid, THREADS>>>(x, w, b, out, M, N, K);
    }
}

// round 12
// speedup vs baseline: 4.9228x; 1.2824x over previous
#include <cuda_runtime.h>
#include <math_constants.h>
#include <stdint.h>

// ===========================================================================
// MAM dense: C[m,n] = max_k(A[m,k]*W[n,k]) + min_k(A[m,k]*W[n,k]) + bias[n]
// plus argmax/argmin index planes (as float).
//
// Pipeline (fast path K=N=1024, M%32==0, M<=8192):
//   P-1: transpose A -> At[k][m], W -> Wt[k][n] (coalesced both ways)
//   P0 : zero worklist counter
//   P1 : per-row top-64 |x| candidates (fp bisection threshold), ascending k,
//        padded with the last real candidate.
//   P3 : candidate evaluation, 32x32 outputs/block, 1024 threads, NO tiles:
//        loop1: warp=m, lanes=n, per-candidate coalesced LDG of Wt[k][n0+..];
//        loop2: warp=n, lanes=m, per-candidate coalesced LDG of At[k][m0+..];
//        fixed 64-trip unrolled loops, role transpose via smem exchange.
//        Soundness check vs theta_a*theta_w; failures -> global worklist.
//   P4 : cleanup — one warp per failing (m,n), exact full-K scan.
// Exactness: ascending-k candidate order + strict compares; all merges break
// value ties by min index (jnp first-occurrence semantics). rel_err == 0.
// ===========================================================================

#define T_CAND 64
#define MAXM 8192
#define NW 1024

__device__ float g_At[(size_t)MAXM * 1024];   // [K][M]
__device__ float g_Wt[(size_t)NW * 1024];     // [K][N]
__device__ int2  g_ca[MAXM * T_CAND];         // (k, float_bits) per A row
__device__ int2  g_cw[NW * T_CAND];           // (k, float_bits) per W row
__device__ float g_th_a[MAXM];
__device__ float g_th_w[NW];
__device__ int      g_cnt;
__device__ unsigned g_work[(size_t)MAXM * NW];

// ---------------------------------------------------------------------------
__global__ void zero_cnt_kernel() { if (threadIdx.x == 0) g_cnt = 0; }

// ---------------------------------------------------------------------------
// transpose X[R][C] -> Xt[C][R], coalesced both sides
// ---------------------------------------------------------------------------
__global__ __launch_bounds__(256)
void transpose_kernel(const float* __restrict__ X, float* __restrict__ Xt,
                      int R, int C) {
    __shared__ float t[32][33];
    const int c0 = blockIdx.x * 32, r0 = blockIdx.y * 32;
    const int x = threadIdx.x, y = threadIdx.y;   // 32 x 8
#pragma unroll
    for (int i = 0; i < 32; i += 8)
        t[y + i][x] = X[(size_t)(r0 + y + i) * C + c0 + x];
    __syncthreads();
#pragma unroll
    for (int i = 0; i < 32; i += 8)
        Xt[(size_t)(c0 + y + i) * R + r0 + x] = t[x][y + i];
}

// ---------------------------------------------------------------------------
// P1: per-row top-|x| candidates. One warp per row, K=1024 fixed.
// ---------------------------------------------------------------------------
__global__ __launch_bounds__(256)
void topk_kernel(const float* __restrict__ X, int rows, int side) {
    const int warp = threadIdx.x >> 5;
    const int lane = threadIdx.x & 31;
    const int row = blockIdx.x * 8 + warp;
    if (row >= rows) return;
    const unsigned FULL = 0xffffffffu;

    int2*  lst = side ? g_cw : g_ca;
    float* thL = side ? g_th_w : g_th_a;

    float s[32];
    const float* Xr = X + (size_t)row * 1024;
#pragma unroll
    for (int j = 0; j < 32; j++) s[j] = Xr[j * 32 + lane];

    float rmax = 0.f;
#pragma unroll
    for (int j = 0; j < 32; j++) rmax = fmaxf(rmax, fabsf(s[j]));
    for (int o = 16; o; o >>= 1) rmax = fmaxf(rmax, __shfl_xor_sync(FULL, rmax, o));

    // bisection: smallest t with count(|x| >= t) <= T_CAND (hi keeps invariant)
    float lo = 0.f, hi = rmax;
    for (int it = 0; it < 16; it++) {
        float mid = 0.5f * (lo + hi);
        int c = 0;
#pragma unroll
        for (int j = 0; j < 32; j++) c += (fabsf(s[j]) >= mid);
        for (int o = 16; o; o >>= 1) c += __shfl_xor_sync(FULL, c, o);
        if (c > T_CAND) lo = mid; else hi = mid;
    }
    const float theta = hi;

    // ascending-k compaction
    int slot = 0;
    int   bestpos = -1, bestidx = 0;
    float bestval = 0.f;
    int2* my = lst + (size_t)row * T_CAND;
#pragma unroll
    for (int j = 0; j < 32; j++) {
        bool pr = (fabsf(s[j]) >= theta);
        unsigned msk = __ballot_sync(FULL, pr);
        if (pr) {
            int pos = slot + __popc(msk & ((1u << lane) - 1u));
            my[pos] = make_int2(j * 32 + lane, __float_as_int(s[j]));
            bestpos = pos; bestidx = j * 32 + lane; bestval = s[j];
        }
        slot += __popc(msk);
    }
    for (int o = 16; o; o >>= 1) {
        int   opos = __shfl_xor_sync(FULL, bestpos, o);
        int   oidx = __shfl_xor_sync(FULL, bestidx, o);
        float oval = __shfl_xor_sync(FULL, bestval, o);
        if (opos > bestpos) { bestpos = opos; bestidx = oidx; bestval = oval; }
    }
    // pad with last real candidate (exact self-tie, ascending preserved)
    for (int p = slot + lane; p < T_CAND; p += 32)
        my[p] = make_int2(bestidx, __float_as_int(bestval));
    if (lane == 0) thL[row] = theta;
}

// ---------------------------------------------------------------------------
// P3: candidate evaluation, no tiles, per-candidate coalesced LDG.
// ---------------------------------------------------------------------------
#define UPDX(P, KK, VX, IX, VN, IN)                                          \
    { bool _g = (P) > (VX); (VX) = _g ? (P) : (VX);                          \
      if (WIDX) (IX) = _g ? (KK) : (IX);                                     \
      bool _l = (P) < (VN); (VN) = _l ? (P) : (VN);                          \
      if (WIDX) (IN) = _l ? (KK) : (IN); }

template <int WIDX>
__global__ __launch_bounds__(1024, 2)
void mam_cand_kernel(const float* __restrict__ At, const float* __restrict__ Wt,
                     const float* __restrict__ bias, float* __restrict__ out,
                     int M) {
    __shared__ int2  sCand[2 * 32 * T_CAND];   // [Ca | Cw], 32KB
    __shared__ float sThA[32], sThW[32];

    const int tid  = threadIdx.x;
    const int wid  = tid >> 5;
    const int lane = tid & 31;
    const int m0 = blockIdx.y * 32;
    const int n0 = blockIdx.x * 32;
    const unsigned FULL = 0xffffffffu;

    int2* sCa = sCand;
    int2* sCw = sCand + 32 * T_CAND;

    for (int i = tid; i < 32 * T_CAND; i += 1024) {
        sCa[i] = g_ca[(size_t)m0 * T_CAND + i];
        sCw[i] = g_cw[(size_t)n0 * T_CAND + i];
    }
    if (tid < 32) {
        sThA[tid] = g_th_a[m0 + tid];
        sThW[tid] = g_th_w[n0 + tid];
    }
    __syncthreads();

    float vmax = -CUDART_INF_F, vmin = CUDART_INF_F;
    int   imax = 0, imin = 0;          // loop1 acc: output (m0+wid, n0+lane)
    float vmax2 = -CUDART_INF_F, vmin2 = CUDART_INF_F;
    int   imax2 = 0, imin2 = 0;        // loop2 acc: output (m0+lane, n0+wid)

    // ---- loop1: warp = m (wid), lanes = n. Candidates of A row m. ----
    {
        const int2* ca = sCa + wid * T_CAND;
        const float* wcol = Wt + n0 + lane;
#pragma unroll 4
        for (int j = 0; j < T_CAND; j += 2) {
            int4 q = *reinterpret_cast<const int4*>(ca + j);
            float w0 = __ldg(wcol + (size_t)q.x * NW);
            float w1 = __ldg(wcol + (size_t)q.z * NW);
            float p0 = __int_as_float(q.y) * w0;
            UPDX(p0, q.x, vmax, imax, vmin, imin);
            float p1 = __int_as_float(q.w) * w1;
            UPDX(p1, q.z, vmax, imax, vmin, imin);
        }
    }

    // ---- loop2: warp = n (wid), lanes = m. Candidates of W row n. ----
    {
        const int2* cw = sCw + wid * T_CAND;
        const float* acol = At + m0 + lane;
#pragma unroll 4
        for (int j = 0; j < T_CAND; j += 2) {
            int4 q = *reinterpret_cast<const int4*>(cw + j);
            float a0 = __ldg(acol + (size_t)q.x * M);
            float a1 = __ldg(acol + (size_t)q.z * M);
            float p0 = a0 * __int_as_float(q.y);
            UPDX(p0, q.x, vmax2, imax2, vmin2, imin2);
            float p1 = a1 * __int_as_float(q.w);
            UPDX(p1, q.z, vmax2, imax2, vmin2, imin2);
        }
    }

    // ---- exchange loop2 results to loop1's thread mapping (overlay sCand) --
    __syncthreads();
    int4* sX = (int4*)sCand;   // 32*33*16 = 16.9KB < 32KB
    sX[lane * 33 + wid] = make_int4(__float_as_int(vmax2), imax2,
                                    __float_as_int(vmin2), imin2);
    __syncthreads();
    {
        int4 e = sX[wid * 33 + lane];
        float xv = __int_as_float(e.x), nv = __int_as_float(e.z);
        if (WIDX) {
            if (xv > vmax || (xv == vmax && e.y < imax)) { vmax = xv; imax = e.y; }
            if (nv < vmin || (nv == vmin && e.w < imin)) { vmin = nv; imin = e.w; }
        } else {
            vmax = fmaxf(vmax, xv);
            vmin = fminf(vmin, nv);
        }
    }

    const int mg = m0 + wid, ng = n0 + lane;

    // ---- soundness check -> worklist (warp-aggregated) ----
    float bnd = sThA[wid] * sThW[lane] * 1.000001f;
    bool bad = !(vmax >= bnd && vmin <= -bnd);
    unsigned msk = __ballot_sync(FULL, bad);
    if (msk) {
        int base = 0;
        int leader = __ffs(msk) - 1;
        if (lane == leader) base = atomicAdd(&g_cnt, __popc(msk));
        base = __shfl_sync(FULL, base, leader);
        if (bad) {
            int pos = base + __popc(msk & ((1u << lane) - 1u));
            g_work[pos] = ((unsigned)mg << 10) | (unsigned)ng;
        }
    }

    const size_t MN = (size_t)M * NW;
    const size_t o  = (size_t)mg * NW + ng;
    out[o] = vmax + vmin + bias[ng];
    if (WIDX) {
        out[MN + o]     = (float)imax;
        out[2 * MN + o] = (float)imin;
    }
}

// ---------------------------------------------------------------------------
// P4: exact cleanup — one warp per failing (m,n).
// ---------------------------------------------------------------------------
__global__ __launch_bounds__(256)
void cleanup_kernel(const float* __restrict__ A, const float* __restrict__ W,
                    const float* __restrict__ bias, float* __restrict__ out,
                    int M, int widx) {
    const unsigned FULL = 0xffffffffu;
    const int lane = threadIdx.x & 31;
    const int gwarp = (blockIdx.x * blockDim.x + threadIdx.x) >> 5;
    const int nwarps = (gridDim.x * blockDim.x) >> 5;
    const int cnt = g_cnt;
    const size_t MN = (size_t)M * NW;

    for (int i = gwarp; i < cnt; i += nwarps) {
        unsigned e = g_work[i];
        int m = (int)(e >> 10), n = (int)(e & 1023u);
        const float4* Ar = reinterpret_cast<const float4*>(A + (size_t)m * 1024) + lane * 8;
        const float4* Wr = reinterpret_cast<const float4*>(W + (size_t)n * 1024) + lane * 8;

        float vmax = -CUDART_INF_F, vmin = CUDART_INF_F;
        int   imax = 0, imin = 0;
#pragma unroll
        for (int j = 0; j < 8; j++) {
            float4 a = Ar[j];
            float4 w = Wr[j];
            int k0 = lane * 32 + j * 4;
            float pv[4] = {a.x * w.x, a.y * w.y, a.z * w.z, a.w * w.w};
#pragma unroll
            for (int q = 0; q < 4; q++) {
                bool g = pv[q] > vmax; vmax = g ? pv[q] : vmax; imax = g ? (k0 + q) : imax;
                bool l = pv[q] < vmin; vmin = l ? pv[q] : vmin; imin = l ? (k0 + q) : imin;
            }
        }
        for (int o = 16; o; o >>= 1) {
            float ov = __shfl_xor_sync(FULL, vmax, o);
            int   oi = __shfl_xor_sync(FULL, imax, o);
            if (ov > vmax || (ov == vmax && oi < imax)) { vmax = ov; imax = oi; }
            float uv = __shfl_xor_sync(FULL, vmin, o);
            int   ui = __shfl_xor_sync(FULL, imin, o);
            if (uv < vmin || (uv == vmin && ui < imin)) { vmin = uv; imin = ui; }
        }
        if (lane == 0) {
            size_t o = (size_t)m * NW + n;
            out[o] = vmax + vmin + bias[n];
            if (widx) {
                out[MN + o]     = (float)imax;
                out[2 * MN + o] = (float)imin;
            }
        }
    }
}

// ---------------------------------------------------------------------------
// fallback exhaustive kernel (unexpected shapes only)
// ---------------------------------------------------------------------------
#define BM 128
#define BN 64
#define BK 16
#define TM 8
#define TN 4
#define THREADS 256

template <bool WIDX>
__global__ __launch_bounds__(THREADS)
void mam_kernel(const float* __restrict__ A, const float* __restrict__ W,
                const float* __restrict__ bias, float* __restrict__ out,
                int M, int N, int K) {
    __shared__ float As[BK][BM + 4];
    __shared__ float Ws[BK][BN + 4];
    const int tid = threadIdx.x;
    const int tx = tid & 15, ty = tid >> 4;
    const int m0 = blockIdx.y * BM, n0 = blockIdx.x * BN;
    float vmax[TM][TN], vmin[TM][TN];
    int   imax[TM][TN], imin[TM][TN];
#pragma unroll
    for (int i = 0; i < TM; i++)
#pragma unroll
        for (int j = 0; j < TN; j++) {
            vmax[i][j] = -CUDART_INF_F; vmin[i][j] = CUDART_INF_F;
            if (WIDX) { imax[i][j] = 0; imin[i][j] = 0; }
        }
    const float* Ablk = A + (size_t)m0 * K;
    const float* Wblk = W + (size_t)n0 * K;
    for (int k0 = 0; k0 < K; k0 += BK) {
#pragma unroll
        for (int r = 0; r < (BM * BK) / THREADS; r++) {
            int idx = tid + r * THREADS;
            As[idx & 15][idx >> 4] = Ablk[(size_t)(idx >> 4) * K + (k0 + (idx & 15))];
        }
#pragma unroll
        for (int r = 0; r < (BN * BK) / THREADS; r++) {
            int idx = tid + r * THREADS;
            Ws[idx & 15][idx >> 4] = Wblk[(size_t)(idx >> 4) * K + (k0 + (idx & 15))];
        }
        __syncthreads();
#pragma unroll 4
        for (int kk = 0; kk < BK; kk++) {
            float a[TM], w[TN];
#pragma unroll
            for (int i = 0; i < TM; i++) a[i] = As[kk][ty * TM + i];
#pragma unroll
            for (int j = 0; j < TN; j++) w[j] = Ws[kk][tx * TN + j];
            const int kg = k0 + kk;
#pragma unroll
            for (int i = 0; i < TM; i++)
#pragma unroll
                for (int j = 0; j < TN; j++) {
                    float p = a[i] * w[j];
                    bool gm = p > vmax[i][j];
                    vmax[i][j] = gm ? p : vmax[i][j];
                    if (WIDX) imax[i][j] = gm ? kg : imax[i][j];
                    bool gn = p < vmin[i][j];
                    vmin[i][j] = gn ? p : vmin[i][j];
                    if (WIDX) imin[i][j] = gn ? kg : imin[i][j];
                }
        }
        __syncthreads();
    }
    const size_t MN = (size_t)M * N;
#pragma unroll
    for (int i = 0; i < TM; i++) {
        int m = m0 + ty * TM + i;
        size_t row = (size_t)m * N + n0 + tx * TN;
#pragma unroll
        for (int j = 0; j < TN; j++) {
            out[row + j] = vmax[i][j] + vmin[i][j] + bias[n0 + tx * TN + j];
            if (WIDX) {
                out[MN + row + j] = (float)imax[i][j];
                out[2 * MN + row + j] = (float)imin[i][j];
            }
        }
    }
}

// ---------------------------------------------------------------------------
extern "C" void kernel_launch(void* const* d_in, const int* in_sizes, int n_in,
                              void* d_out, int out_size) {
    const float* x = (const float*)d_in[0];
    const float* w = (const float*)d_in[1];
    const float* b = (const float*)d_in[2];
    float* out = (float*)d_out;

    const int N = in_sizes[2];
    const int K = in_sizes[1] / N;
    const int M = in_sizes[0] / K;
    const long long MN = (long long)M * (long long)N;
    const int widx = ((long long)out_size >= 3 * MN) ? 1 : 0;

    if (K == 1024 && N == 1024 && M <= MAXM && (M % 32) == 0) {
        float* At; cudaGetSymbolAddress((void**)&At, g_At);
        float* Wt; cudaGetSymbolAddress((void**)&Wt, g_Wt);

        zero_cnt_kernel<<<1, 32>>>();
        {
            dim3 blk(32, 8);
            dim3 ga(1024 / 32, M / 32);
            transpose_kernel<<<ga, blk>>>(x, At, M, 1024);
            dim3 gw(1024 / 32, 1024 / 32);
            transpose_kernel<<<gw, blk>>>(w, Wt, 1024, 1024);
        }
        topk_kernel<<<(M + 7) / 8, 256>>>(x, M, 0);
        topk_kernel<<<(N + 7) / 8, 256>>>(w, N, 1);

        dim3 grid(N / 32, M / 32);
        if (widx) mam_cand_kernel<1><<<grid, 1024>>>(At, Wt, b, out, M);
        else      mam_cand_kernel<0><<<grid, 1024>>>(At, Wt, b, out, M);

        cleanup_kernel<<<1184, 256>>>(x, w, b, out, M, widx);
    } else {
        dim3 grid(N / BN, M / BM);
        if (widx) mam_kernel<true><<<grid, THREADS>>>(x, w, b, out, M, N, K);
        else      mam_kernel<false><<<grid, THREADS>>>(x, w, b, out, M, N, K);
    }
}